// round 12
// baseline (speedup 1.0000x reference)
#include <cuda_runtime.h>
#include <cuda_bf16.h>
#include <cstdint>

#define DIM    384
#define NTOK   50176      // 1024 windows * 49 tokens
#define NWIN   1024
#define HEADS  12
#define HD     32
#define NWN    49
#define QSCALE 0.17677669529663689f  // 1/sqrt(32)

// ---------------- scratch (static device memory, no allocs) ----------------
__device__ __nv_bfloat16 g_xw [(size_t)NTOK * DIM];
__device__ __nv_bfloat16 g_qkv[(size_t)NTOK * 3 * DIM];
__device__ __nv_bfloat16 g_att[(size_t)NTOK * DIM];
__device__ float         g_y  [(size_t)NTOK * DIM];
__device__ __nv_bfloat16 g_m  [(size_t)NTOK * DIM];
__device__ __nv_bfloat16 g_h1 [(size_t)NTOK * 4 * DIM];
// weights stored TRANSPOSED: [N, K] K-major bf16
__device__ __nv_bfloat16 g_wqkv [3 * DIM * DIM];
__device__ __nv_bfloat16 g_wproj[DIM * DIM];
__device__ __nv_bfloat16 g_wfc1 [4 * DIM * DIM];
__device__ __nv_bfloat16 g_wfc2 [DIM * 4 * DIM];
__device__ float         g_bqkv [3 * DIM];              // q-prescaled qkv bias
__device__ __nv_bfloat16 g_tbl  [192 * 4096];           // bias+mask (bf16): [wcls][head][64][64]

// ---------------- helpers ----------------
__device__ __forceinline__ uint32_t smem_u32(const void* p) {
    uint32_t a;
    asm("{ .reg .u64 t; cvta.to.shared.u64 t, %1; cvt.u32.u64 %0, t; }" : "=r"(a) : "l"(p));
    return a;
}

#define CP_ASYNC16(dst, src) \
    asm volatile("cp.async.cg.shared.global [%0], [%1], 16;" :: "r"(dst), "l"(src) : "memory")
#define CP_COMMIT() asm volatile("cp.async.commit_group;" ::: "memory")

__device__ __forceinline__ void ldmatrix_x4(uint32_t* r, uint32_t addr) {
    asm volatile("ldmatrix.sync.aligned.m8n8.x4.shared.b16 {%0,%1,%2,%3}, [%4];"
                 : "=r"(r[0]), "=r"(r[1]), "=r"(r[2]), "=r"(r[3]) : "r"(addr));
}
__device__ __forceinline__ void ldmatrix_x4_trans(uint32_t* r, uint32_t addr) {
    asm volatile("ldmatrix.sync.aligned.m8n8.x4.trans.shared.b16 {%0,%1,%2,%3}, [%4];"
                 : "=r"(r[0]), "=r"(r[1]), "=r"(r[2]), "=r"(r[3]) : "r"(addr));
}

__device__ __forceinline__ void mma_16816(float* c, const uint32_t* a, uint32_t b0, uint32_t b1) {
    asm volatile(
        "mma.sync.aligned.m16n8k16.row.col.f32.bf16.bf16.f32 "
        "{%0,%1,%2,%3}, {%4,%5,%6,%7}, {%8,%9}, {%0,%1,%2,%3};"
        : "+f"(c[0]), "+f"(c[1]), "+f"(c[2]), "+f"(c[3])
        : "r"(a[0]), "r"(a[1]), "r"(a[2]), "r"(a[3]), "r"(b0), "r"(b1));
}

__device__ __forceinline__ uint32_t pack_bf16(float lo, float hi) {
    __nv_bfloat162 p = __float22bfloat162_rn(make_float2(lo, hi));
    return *reinterpret_cast<uint32_t*>(&p);
}

// window-order row -> original token index
__device__ __forceinline__ int map_row(int r) {
    int win = r / NWN, n = r % NWN;
    int b = win >> 4, wIdx = win & 15;
    int hs = (wIdx >> 2) * 7 + n / 7;
    int ws = (wIdx & 3) * 7 + n % 7;
    int h = hs + 3; if (h >= 28) h -= 28;
    int w = ws + 3; if (w >= 28) w -= 28;
    return b * 784 + h * 28 + w;
}

// ---------------- merged setup: weight transpose-casts + bias prescale + bias/mask table ----
__global__ __launch_bounds__(256)
void cvt_all(const float* __restrict__ qkv_w, const float* __restrict__ proj_w,
             const float* __restrict__ fc1_w, const float* __restrict__ fc2_w,
             const float* __restrict__ qkv_b, const float* __restrict__ rpb) {
    const int t = blockIdx.x;
    const int tid = threadIdx.x;

    if (t >= 1728) {                         // table part
        const int b = t - 1728;              // 0..191 = wcls*12 + head
        const int wIdx = b / 12, head = b % 12;
        for (int i = tid; i < 4096; i += 256) {
            int r = i >> 6, c = i & 63;
            float v = -1e30f;
            if (r < NWN && c < NWN) {
                int rh = r / 7, rw = r % 7, chh = c / 7, cww = c % 7;
                int di = rh - chh + 6, dj = rw - cww + 6;
                v = rpb[(di * 13 + dj) * HEADS + head];
                int hh_r = (wIdx >> 2) * 7 + rh, ww_r = (wIdx & 3) * 7 + rw;
                int hh_c = (wIdx >> 2) * 7 + chh, ww_c = (wIdx & 3) * 7 + cww;
                int clr = (hh_r < 21 ? 0 : (hh_r < 25 ? 1 : 2)) * 3 + (ww_r < 21 ? 0 : (ww_r < 25 ? 1 : 2));
                int clc = (hh_c < 21 ? 0 : (hh_c < 25 ? 1 : 2)) * 3 + (ww_c < 21 ? 0 : (ww_c < 25 ? 1 : 2));
                if (clr != clc) v -= 100.f;
            }
            g_tbl[((size_t)b << 12) + i] = __float2bfloat16(v);
        }
        return;
    }

    __shared__ float tile[32][33];
    const int tx = tid & 31, ty = tid >> 5;

    if (t < 5) {
        int idx = t * 256 + tid;
        if (idx < 3 * DIM)
            g_bqkv[idx] = qkv_b[idx] * (idx < DIM ? QSCALE : 1.f);
    }

    const float* src; __nv_bfloat16* dst;
    int K, N, tn, tk;
    float scale0 = 1.f;
    if (t < 432)       { src = qkv_w;  dst = g_wqkv;  K = 384;  N = 1152; tn = t % 36;          tk = t / 36;          scale0 = QSCALE; }
    else if (t < 576)  { src = proj_w; dst = g_wproj; K = 384;  N = 384;  tn = (t - 432) % 12;  tk = (t - 432) / 12; }
    else if (t < 1152) { src = fc1_w;  dst = g_wfc1;  K = 384;  N = 1536; tn = (t - 576) % 48;  tk = (t - 576) / 48; }
    else               { src = fc2_w;  dst = g_wfc2;  K = 1536; N = 384;  tn = (t - 1152) % 12; tk = (t - 1152) / 12; }

    int k0 = tk * 32, n0 = tn * 32;
#pragma unroll
    for (int i = 0; i < 4; i++)
        tile[ty + i * 8][tx] = src[(size_t)(k0 + ty + i * 8) * N + n0 + tx];
    __syncthreads();
#pragma unroll
    for (int i = 0; i < 4; i++) {
        int n = n0 + ty + i * 8;
        float s = (n < 384) ? scale0 : 1.f;
        dst[(size_t)n * K + k0 + tx] = __float2bfloat16(tile[tx][ty + i * 8] * s);
    }
}

// ---------------- LayerNorm: one warp per row, no smem, no syncthreads ----------------
template<bool PERM>
__global__ __launch_bounds__(256)
void ln_kernel(const float* __restrict__ in,
               const float* __restrict__ gamma,
               const float* __restrict__ beta,
               __nv_bfloat16* __restrict__ out) {
    const int wid = threadIdx.x >> 5, lane = threadIdx.x & 31;
    const int r = blockIdx.x * 8 + wid;
    const int src = PERM ? map_row(r) : r;
    const float* row = in + (size_t)src * DIM;

    float4 v[3];
    float s = 0.f, s2 = 0.f;
#pragma unroll
    for (int i = 0; i < 3; i++) {
        v[i] = *reinterpret_cast<const float4*>(&row[lane * 4 + i * 128]);
        s  += v[i].x + v[i].y + v[i].z + v[i].w;
        s2 += v[i].x * v[i].x + v[i].y * v[i].y + v[i].z * v[i].z + v[i].w * v[i].w;
    }
#pragma unroll
    for (int o = 16; o; o >>= 1) {
        s  += __shfl_xor_sync(0xffffffffu, s,  o);
        s2 += __shfl_xor_sync(0xffffffffu, s2, o);
    }
    float mean = s * (1.f / DIM);
    float rstd = rsqrtf(s2 * (1.f / DIM) - mean * mean + 1e-5f);

#pragma unroll
    for (int i = 0; i < 3; i++) {
        int c = lane * 4 + i * 128;
        float4 g = *reinterpret_cast<const float4*>(&gamma[c]);
        float4 b = *reinterpret_cast<const float4*>(&beta[c]);
        float o0 = (v[i].x - mean) * rstd * g.x + b.x;
        float o1 = (v[i].y - mean) * rstd * g.y + b.y;
        float o2 = (v[i].z - mean) * rstd * g.z + b.z;
        float o3 = (v[i].w - mean) * rstd * g.w + b.w;
        uint2 pk = make_uint2(pack_bf16(o0, o1), pack_bf16(o2, o3));
        *reinterpret_cast<uint2*>(&out[(size_t)r * DIM + c]) = pk;
    }
}

// ---------------- mma.sync GEMM: 128x128x32 CTA tile, 8 warps of 32x64, 4 stages ----------------
// inner loop batches all 4 B ldmatrix loads per k-half before the 16 MMAs (latency hiding)
#define STAGE_B 16384
#define NSTAGE  4
#define GEMM_SMEM (NSTAGE * STAGE_B)

template<int MODE>
__global__ __launch_bounds__(256, 2)
void mma_gemm(const __nv_bfloat16* __restrict__ A,
              const __nv_bfloat16* __restrict__ B,
              const float* __restrict__ bias,
              const float* __restrict__ resid,
              __nv_bfloat16* __restrict__ outb,
              float* __restrict__ outf,
              int N, int K) {
    extern __shared__ __align__(1024) char smem[];   // per stage: A 8KB | B 8KB
    const uint32_t sbase = smem_u32(smem);

    const int tid = threadIdx.x;
    const int wid = tid >> 5, lane = tid & 31;
    const int warpM = wid >> 1;
    const int warpN = wid & 1;
    const int m0 = blockIdx.y * 128, n0 = blockIdx.x * 128;

    float acc[2][8][4];
#pragma unroll
    for (int i = 0; i < 2; i++)
#pragma unroll
        for (int j = 0; j < 8; j++)
#pragma unroll
            for (int q = 0; q < 4; q++) acc[i][j][q] = 0.f;

    const int nch = K >> 5;
    const int lr = tid >> 2;
    const int lc = tid & 3;
    auto load_stage = [&](int s, int c) {
        uint32_t st = sbase + s * STAGE_B;
        int k0 = c * 32;
#pragma unroll
        for (int i = 0; i < 2; i++) {
            int r = lr + i * 64;
            uint32_t sw = (uint32_t)((lc ^ ((r >> 1) & 3)) << 4);
            CP_ASYNC16(st + r * 64 + sw, A + (size_t)(m0 + r) * K + k0 + lc * 8);
        }
#pragma unroll
        for (int i = 0; i < 2; i++) {
            int r = lr + i * 64;
            uint32_t sw = (uint32_t)((lc ^ ((r >> 1) & 3)) << 4);
            CP_ASYNC16(st + 8192 + r * 64 + sw, B + (size_t)(n0 + r) * K + k0 + lc * 8);
        }
        CP_COMMIT();
    };

    load_stage(0, 0);
    if (nch > 1) load_stage(1, 1);
    if (nch > 2) load_stage(2, 2);

    const int lrow = lane & 15;
    const int lhalf = lane >> 4;

    for (int c = 0; c < nch; c++) {
        if (c + 2 < nch)      asm volatile("cp.async.wait_group 2;" ::: "memory");
        else if (c + 1 < nch) asm volatile("cp.async.wait_group 1;" ::: "memory");
        else                  asm volatile("cp.async.wait_group 0;" ::: "memory");
        __syncthreads();
        if (c + 3 < nch) load_stage((c + 3) & 3, c + 3);

        uint32_t sA = sbase + (c & 3) * STAGE_B;
        uint32_t sB = sA + 8192;

        // preload all A fragments for both k-halves (4 LDSM, no consumer yet)
        uint32_t a[2][2][4];
#pragma unroll
        for (int kh = 0; kh < 2; kh++)
#pragma unroll
            for (int mt = 0; mt < 2; mt++) {
                int r = warpM * 32 + mt * 16 + lrow;
                int chunk = kh * 2 + lhalf;
                ldmatrix_x4(a[kh][mt], sA + r * 64 + (uint32_t)((chunk ^ ((r >> 1) & 3)) << 4));
            }
#pragma unroll
        for (int kh = 0; kh < 2; kh++) {
            int chunk = kh * 2 + lhalf;
            // batch ALL 4 B ldmatrix loads first (back-to-back, latency overlapped)
            uint32_t b[4][4];
#pragma unroll
            for (int np = 0; np < 4; np++) {
                int r = warpN * 64 + np * 16 + lrow;
                ldmatrix_x4(b[np], sB + r * 64 + (uint32_t)((chunk ^ ((r >> 1) & 3)) << 4));
            }
            // then issue the 16 MMAs as a dense burst
#pragma unroll
            for (int np = 0; np < 4; np++)
#pragma unroll
                for (int mt = 0; mt < 2; mt++) {
                    mma_16816(acc[mt][2 * np],     a[kh][mt], b[np][0], b[np][2]);
                    mma_16816(acc[mt][2 * np + 1], a[kh][mt], b[np][1], b[np][3]);
                }
        }
    }

    // ---------------- fused epilogue on register accumulators ----------------
    const int colq = (lane & 3) * 2;
#pragma unroll
    for (int mt = 0; mt < 2; mt++) {
        int grow0 = m0 + warpM * 32 + mt * 16 + (lane >> 2);
        int grow1 = grow0 + 8;
        int dst0 = (MODE == 1) ? map_row(grow0) : grow0;
        int dst1 = (MODE == 1) ? map_row(grow1) : grow1;
#pragma unroll
        for (int nt = 0; nt < 8; nt++) {
            int gc = n0 + warpN * 64 + nt * 8 + colq;
            float b0 = bias[gc], b1 = bias[gc + 1];
            float v00 = acc[mt][nt][0] + b0, v01 = acc[mt][nt][1] + b1;
            float v10 = acc[mt][nt][2] + b0, v11 = acc[mt][nt][3] + b1;
            if (MODE == 0) {
                *reinterpret_cast<__nv_bfloat162*>(&outb[(size_t)grow0 * N + gc]) =
                    __nv_bfloat162(__float2bfloat16(v00), __float2bfloat16(v01));
                *reinterpret_cast<__nv_bfloat162*>(&outb[(size_t)grow1 * N + gc]) =
                    __nv_bfloat162(__float2bfloat16(v10), __float2bfloat16(v11));
            } else if (MODE == 1) {
                const float2 r0 = *reinterpret_cast<const float2*>(&resid[(size_t)dst0 * N + gc]);
                const float2 r1 = *reinterpret_cast<const float2*>(&resid[(size_t)dst1 * N + gc]);
                *reinterpret_cast<float2*>(&outf[(size_t)dst0 * N + gc]) =
                    make_float2(v00 + r0.x, v01 + r0.y);
                *reinterpret_cast<float2*>(&outf[(size_t)dst1 * N + gc]) =
                    make_float2(v10 + r1.x, v11 + r1.y);
            } else if (MODE == 2) {
                v00 = 0.5f * v00 * (1.0f + erff(v00 * 0.7071067811865475f));
                v01 = 0.5f * v01 * (1.0f + erff(v01 * 0.7071067811865475f));
                v10 = 0.5f * v10 * (1.0f + erff(v10 * 0.7071067811865475f));
                v11 = 0.5f * v11 * (1.0f + erff(v11 * 0.7071067811865475f));
                *reinterpret_cast<__nv_bfloat162*>(&outb[(size_t)grow0 * N + gc]) =
                    __nv_bfloat162(__float2bfloat16(v00), __float2bfloat16(v01));
                *reinterpret_cast<__nv_bfloat162*>(&outb[(size_t)grow1 * N + gc]) =
                    __nv_bfloat162(__float2bfloat16(v10), __float2bfloat16(v11));
            } else {
                const float2 r0 = *reinterpret_cast<const float2*>(&resid[(size_t)grow0 * N + gc]);
                const float2 r1 = *reinterpret_cast<const float2*>(&resid[(size_t)grow1 * N + gc]);
                *reinterpret_cast<float2*>(&outf[(size_t)grow0 * N + gc]) =
                    make_float2(v00 + r0.x, v01 + r0.y);
                *reinterpret_cast<float2*>(&outf[(size_t)grow1 * N + gc]) =
                    make_float2(v10 + r1.x, v11 + r1.y);
            }
        }
    }
}

// ---------------- tensor-core windowed attention: block = (2 windows, head) ----------------
#define TBL_STRIDE 144    // bytes per table row in smem (36 words -> conflict-free reads)
__global__ __launch_bounds__(256)
void attn_mma(const __nv_bfloat16* __restrict__ qkv,
              const __nv_bfloat16* __restrict__ tbl,
              __nv_bfloat16* __restrict__ out) {
    __shared__ __align__(1024) char sq[2][4096];
    __shared__ __align__(1024) char sk[2][4096];
    __shared__ __align__(1024) char sv[2][4096];
    __shared__ __align__(16)   char stbl[64 * TBL_STRIDE];

    const int tid = threadIdx.x;
    const int sub = tid >> 7;                 // 0/1 half-block
    const int t2 = tid & 127;
    const int lane = tid & 31, w4 = (tid >> 5) & 3;
    const int win = blockIdx.x + sub * 512;
    const int head = blockIdx.y;
    const uint32_t qb = smem_u32(sq[sub]), kb = smem_u32(sk[sub]), vb = smem_u32(sv[sub]);
    const uint32_t tbase = smem_u32(stbl);

    // stage the shared table slice (8KB) once for both windows
    {
        const uint4* g = reinterpret_cast<const uint4*>(
            tbl + (((size_t)((blockIdx.x & 15) * 12 + head)) << 12));
#pragma unroll
        for (int i = tid; i < 512; i += 256) {
            int r = i >> 3, c16 = i & 7;
            *reinterpret_cast<uint4*>(stbl + r * TBL_STRIDE + c16 * 16) = g[i];
        }
    }

    const size_t base = (size_t)win * NWN * 1152 + head * HD;
    for (int i = t2; i < 256; i += 128) {
        int r = i >> 2, c = i & 3;
        uint4 vq = make_uint4(0, 0, 0, 0), vk = vq, vv = vq;
        if (r < NWN) {
            vq = reinterpret_cast<const uint4*>(qkv + base + (size_t)r * 1152)[c];
            vk = reinterpret_cast<const uint4*>(qkv + base + 384 + (size_t)r * 1152)[c];
            vv = reinterpret_cast<const uint4*>(qkv + base + 768 + (size_t)r * 1152)[c];
        }
        uint32_t sw = (uint32_t)((c ^ ((r >> 1) & 3)) << 4);
        *reinterpret_cast<uint4*>(sq[sub] + r * 64 + sw) = vq;
        *reinterpret_cast<uint4*>(sk[sub] + r * 64 + sw) = vk;
        *reinterpret_cast<uint4*>(sv[sub] + r * 64 + sw) = vv;
    }
    __syncthreads();

    const int lrow = lane & 15, lhalf = lane >> 4;

    // ---- S = q k^T (16x64 per warp) ----
    float sacc[8][4];
#pragma unroll
    for (int t = 0; t < 8; t++)
#pragma unroll
        for (int q = 0; q < 4; q++) sacc[t][q] = 0.f;

    uint32_t af[2][4];
#pragma unroll
    for (int kh = 0; kh < 2; kh++) {
        int r = w4 * 16 + lrow;
        int chunk = kh * 2 + lhalf;
        ldmatrix_x4(af[kh], qb + r * 64 + (uint32_t)((chunk ^ ((r >> 1) & 3)) << 4));
    }
#pragma unroll
    for (int kh = 0; kh < 2; kh++) {
        int chunk = kh * 2 + lhalf;
        uint32_t b[4][4];
#pragma unroll
        for (int np = 0; np < 4; np++) {
            int r = np * 16 + lrow;
            ldmatrix_x4(b[np], kb + r * 64 + (uint32_t)((chunk ^ ((r >> 1) & 3)) << 4));
        }
#pragma unroll
        for (int np = 0; np < 4; np++) {
            mma_16816(sacc[2 * np],     af[kh], b[np][0], b[np][2]);
            mma_16816(sacc[2 * np + 1], af[kh], b[np][1], b[np][3]);
        }
    }

    // ---- bias + mask from smem-staged bf16 table (conflict-free) ----
    const int r0 = w4 * 16 + (lane >> 2), r1 = r0 + 8;
    const int c0 = 2 * (lane & 3);
    const uint32_t tb0 = tbase + r0 * TBL_STRIDE + c0 * 2;
#pragma unroll
    for (int t = 0; t < 8; t++) {
        uint32_t u0, u1;
        asm volatile("ld.shared.b32 %0, [%1];" : "=r"(u0) : "r"(tb0 + 16 * t));
        asm volatile("ld.shared.b32 %0, [%1];" : "=r"(u1) : "r"(tb0 + 8 * TBL_STRIDE + 16 * t));
        float2 b0 = __bfloat1622float2(*reinterpret_cast<__nv_bfloat162*>(&u0));
        float2 b1 = __bfloat1622float2(*reinterpret_cast<__nv_bfloat162*>(&u1));
        sacc[t][0] += b0.x; sacc[t][1] += b0.y;
        sacc[t][2] += b1.x; sacc[t][3] += b1.y;
    }

    // ---- softmax on registers ----
    float mx0 = -1e30f, mx1 = -1e30f;
#pragma unroll
    for (int t = 0; t < 8; t++) {
        mx0 = fmaxf(mx0, fmaxf(sacc[t][0], sacc[t][1]));
        mx1 = fmaxf(mx1, fmaxf(sacc[t][2], sacc[t][3]));
    }
    mx0 = fmaxf(mx0, __shfl_xor_sync(0xffffffffu, mx0, 1));
    mx0 = fmaxf(mx0, __shfl_xor_sync(0xffffffffu, mx0, 2));
    mx1 = fmaxf(mx1, __shfl_xor_sync(0xffffffffu, mx1, 1));
    mx1 = fmaxf(mx1, __shfl_xor_sync(0xffffffffu, mx1, 2));
    float s0 = 0.f, s1 = 0.f;
#pragma unroll
    for (int t = 0; t < 8; t++) {
        float e0 = __expf(sacc[t][0] - mx0); sacc[t][0] = e0; s0 += e0;
        float e1 = __expf(sacc[t][1] - mx0); sacc[t][1] = e1; s0 += e1;
        float e2 = __expf(sacc[t][2] - mx1); sacc[t][2] = e2; s1 += e2;
        float e3 = __expf(sacc[t][3] - mx1); sacc[t][3] = e3; s1 += e3;
    }
    s0 += __shfl_xor_sync(0xffffffffu, s0, 1);
    s0 += __shfl_xor_sync(0xffffffffu, s0, 2);
    s1 += __shfl_xor_sync(0xffffffffu, s1, 1);
    s1 += __shfl_xor_sync(0xffffffffu, s1, 2);
    float inv0 = 1.f / s0, inv1 = 1.f / s1;
#pragma unroll
    for (int t = 0; t < 8; t++) {
        sacc[t][0] *= inv0; sacc[t][1] *= inv0;
        sacc[t][2] *= inv1; sacc[t][3] *= inv1;
    }

    // ---- out = P V : P repacked as A frags; V natural layout via ldmatrix.trans ----
    float oacc[4][4];
#pragma unroll
    for (int t = 0; t < 4; t++)
#pragma unroll
        for (int q = 0; q < 4; q++) oacc[t][q] = 0.f;

#pragma unroll
    for (int j = 0; j < 4; j++) {
        uint32_t pa[4];
        pa[0] = pack_bf16(sacc[2 * j][0],     sacc[2 * j][1]);
        pa[1] = pack_bf16(sacc[2 * j][2],     sacc[2 * j][3]);
        pa[2] = pack_bf16(sacc[2 * j + 1][0], sacc[2 * j + 1][1]);
        pa[3] = pack_bf16(sacc[2 * j + 1][2], sacc[2 * j + 1][3]);
        int vr = j * 16 + ((lane >> 3) & 1) * 8 + (lane & 7);
        uint32_t t4[2][4];
#pragma unroll
        for (int dblk = 0; dblk < 2; dblk++) {
            int chunk = dblk * 2 + (lane >> 4);
            ldmatrix_x4_trans(t4[dblk], vb + vr * 64 + (uint32_t)((chunk ^ ((vr >> 1) & 3)) << 4));
        }
#pragma unroll
        for (int dblk = 0; dblk < 2; dblk++) {
            mma_16816(oacc[2 * dblk],     pa, t4[dblk][0], t4[dblk][1]);
            mma_16816(oacc[2 * dblk + 1], pa, t4[dblk][2], t4[dblk][3]);
        }
    }

    if (r0 < NWN) {
        size_t ob = ((size_t)win * NWN + r0) * DIM + head * HD;
#pragma unroll
        for (int t = 0; t < 4; t++) {
            int d = 8 * t + c0;
            *reinterpret_cast<__nv_bfloat162*>(&out[ob + d]) =
                __nv_bfloat162(__float2bfloat16(oacc[t][0]), __float2bfloat16(oacc[t][1]));
        }
    }
    if (r1 < NWN) {
        size_t ob = ((size_t)win * NWN + r1) * DIM + head * HD;
#pragma unroll
        for (int t = 0; t < 4; t++) {
            int d = 8 * t + c0;
            *reinterpret_cast<__nv_bfloat162*>(&out[ob + d]) =
                __nv_bfloat162(__float2bfloat16(oacc[t][2]), __float2bfloat16(oacc[t][3]));
        }
    }
}

// ---------------- launch ----------------
extern "C" void kernel_launch(void* const* d_in, const int* in_sizes, int n_in,
                              void* d_out, int out_size) {
    const float* x      = (const float*)d_in[0];
    const float* n1g    = (const float*)d_in[1];
    const float* n1b    = (const float*)d_in[2];
    const float* qkv_w  = (const float*)d_in[3];
    const float* qkv_b  = (const float*)d_in[4];
    const float* proj_w = (const float*)d_in[5];
    const float* proj_b = (const float*)d_in[6];
    const float* rpb    = (const float*)d_in[7];
    const float* n2g    = (const float*)d_in[8];
    const float* n2b    = (const float*)d_in[9];
    const float* fc1_w  = (const float*)d_in[10];
    const float* fc1_b  = (const float*)d_in[11];
    const float* fc2_w  = (const float*)d_in[12];
    const float* fc2_b  = (const float*)d_in[13];
    float* out = (float*)d_out;

    __nv_bfloat16 *xw, *qkv, *att, *m, *h1, *wqkv, *wproj, *wfc1, *wfc2, *tbl;
    float *y, *bqkv;
    cudaGetSymbolAddress((void**)&xw,    g_xw);
    cudaGetSymbolAddress((void**)&qkv,   g_qkv);
    cudaGetSymbolAddress((void**)&att,   g_att);
    cudaGetSymbolAddress((void**)&y,     g_y);
    cudaGetSymbolAddress((void**)&m,     g_m);
    cudaGetSymbolAddress((void**)&h1,    g_h1);
    cudaGetSymbolAddress((void**)&wqkv,  g_wqkv);
    cudaGetSymbolAddress((void**)&wproj, g_wproj);
    cudaGetSymbolAddress((void**)&wfc1,  g_wfc1);
    cudaGetSymbolAddress((void**)&wfc2,  g_wfc2);
    cudaGetSymbolAddress((void**)&bqkv,  g_bqkv);
    cudaGetSymbolAddress((void**)&tbl,   g_tbl);

    cudaFuncSetAttribute(mma_gemm<0>, cudaFuncAttributeMaxDynamicSharedMemorySize, GEMM_SMEM);
    cudaFuncSetAttribute(mma_gemm<1>, cudaFuncAttributeMaxDynamicSharedMemorySize, GEMM_SMEM);
    cudaFuncSetAttribute(mma_gemm<2>, cudaFuncAttributeMaxDynamicSharedMemorySize, GEMM_SMEM);
    cudaFuncSetAttribute(mma_gemm<3>, cudaFuncAttributeMaxDynamicSharedMemorySize, GEMM_SMEM);

    // side stream + events, created once on the (uncaptured) correctness call
    static cudaStream_t s1 = nullptr;
    static cudaEvent_t evFork = nullptr, evJoin = nullptr;
    if (!s1) {
        cudaStreamCreateWithFlags(&s1, cudaStreamNonBlocking);
        cudaEventCreateWithFlags(&evFork, cudaEventDisableTiming);
        cudaEventCreateWithFlags(&evJoin, cudaEventDisableTiming);
    }

    // fork: cvt_all (weights/table, independent of x) runs concurrently with LN1
    cudaEventRecord(evFork, 0);
    cudaStreamWaitEvent(s1, evFork, 0);
    cvt_all<<<1920, 256, 0, s1>>>(qkv_w, proj_w, fc1_w, fc2_w, qkv_b, rpb);
    cudaEventRecord(evJoin, s1);

    // LN1 + shift + window partition (warp per row) on main stream
    ln_kernel<true><<<NTOK / 8, 256>>>(x, n1g, n1b, xw);

    // join before QKV (needs weights)
    cudaStreamWaitEvent(0, evJoin, 0);

    // QKV (q-scale folded into weights/bias)
    mma_gemm<0><<<dim3(9, 392), 256, GEMM_SMEM>>>(xw, wqkv, bqkv, nullptr, qkv, nullptr, 3 * DIM, DIM);

    // attention (tensor cores; 2 windows/block sharing one smem-staged table slice)
    attn_mma<<<dim3(512, HEADS), 256>>>(qkv, tbl, att);

    // proj + window reverse + unshift + residual
    mma_gemm<1><<<dim3(3, 392), 256, GEMM_SMEM>>>(att, wproj, proj_b, x, nullptr, y, DIM, DIM);

    // LN2
    ln_kernel<false><<<NTOK / 8, 256>>>(y, n2g, n2b, m);

    // FC1 + GELU
    mma_gemm<2><<<dim3(12, 392), 256, GEMM_SMEM>>>(m, wfc1, fc1_b, nullptr, h1, nullptr, 4 * DIM, DIM);

    // FC2 + residual -> output
    mma_gemm<3><<<dim3(3, 392), 256, GEMM_SMEM>>>(h1, wfc2, fc2_b, y, nullptr, out, DIM, 4 * DIM);
}

// round 13
// speedup vs baseline: 1.0099x; 1.0099x over previous
#include <cuda_runtime.h>
#include <cuda_bf16.h>
#include <cstdint>

#define DIM    384
#define NTOK   50176      // 1024 windows * 49 tokens
#define NWIN   1024
#define HEADS  12
#define HD     32
#define NWN    49
#define QSCALE 0.17677669529663689f  // 1/sqrt(32)

// ---------------- scratch (static device memory, no allocs) ----------------
__device__ __nv_bfloat16 g_xw [(size_t)NTOK * DIM];
__device__ __nv_bfloat16 g_qkv[(size_t)NTOK * 3 * DIM];
__device__ __nv_bfloat16 g_att[(size_t)NTOK * DIM];
__device__ float         g_y  [(size_t)NTOK * DIM];
__device__ __nv_bfloat16 g_m  [(size_t)NTOK * DIM];
__device__ __nv_bfloat16 g_h1 [(size_t)NTOK * 4 * DIM];
// weights stored TRANSPOSED: [N, K] K-major bf16
__device__ __nv_bfloat16 g_wqkv [3 * DIM * DIM];
__device__ __nv_bfloat16 g_wproj[DIM * DIM];
__device__ __nv_bfloat16 g_wfc1 [4 * DIM * DIM];
__device__ __nv_bfloat16 g_wfc2 [DIM * 4 * DIM];
__device__ float         g_bqkv [3 * DIM];              // q-prescaled qkv bias
__device__ __nv_bfloat16 g_tbl  [192 * 4096];           // bias+mask (bf16): [wcls][head][64][64]

// ---------------- helpers ----------------
__device__ __forceinline__ uint32_t smem_u32(const void* p) {
    uint32_t a;
    asm("{ .reg .u64 t; cvta.to.shared.u64 t, %1; cvt.u32.u64 %0, t; }" : "=r"(a) : "l"(p));
    return a;
}

#define CP_ASYNC16(dst, src) \
    asm volatile("cp.async.cg.shared.global [%0], [%1], 16;" :: "r"(dst), "l"(src) : "memory")
#define CP_ASYNC16_Z(dst, src, n) \
    asm volatile("cp.async.cg.shared.global [%0], [%1], 16, %2;" :: "r"(dst), "l"(src), "r"(n) : "memory")
#define CP_COMMIT() asm volatile("cp.async.commit_group;" ::: "memory")
#define CP_WAIT0()  asm volatile("cp.async.wait_group 0;" ::: "memory")

__device__ __forceinline__ void ldmatrix_x4(uint32_t* r, uint32_t addr) {
    asm volatile("ldmatrix.sync.aligned.m8n8.x4.shared.b16 {%0,%1,%2,%3}, [%4];"
                 : "=r"(r[0]), "=r"(r[1]), "=r"(r[2]), "=r"(r[3]) : "r"(addr));
}
__device__ __forceinline__ void ldmatrix_x4_trans(uint32_t* r, uint32_t addr) {
    asm volatile("ldmatrix.sync.aligned.m8n8.x4.trans.shared.b16 {%0,%1,%2,%3}, [%4];"
                 : "=r"(r[0]), "=r"(r[1]), "=r"(r[2]), "=r"(r[3]) : "r"(addr));
}

__device__ __forceinline__ void mma_16816(float* c, const uint32_t* a, uint32_t b0, uint32_t b1) {
    asm volatile(
        "mma.sync.aligned.m16n8k16.row.col.f32.bf16.bf16.f32 "
        "{%0,%1,%2,%3}, {%4,%5,%6,%7}, {%8,%9}, {%0,%1,%2,%3};"
        : "+f"(c[0]), "+f"(c[1]), "+f"(c[2]), "+f"(c[3])
        : "r"(a[0]), "r"(a[1]), "r"(a[2]), "r"(a[3]), "r"(b0), "r"(b1));
}

__device__ __forceinline__ uint32_t pack_bf16(float lo, float hi) {
    __nv_bfloat162 p = __float22bfloat162_rn(make_float2(lo, hi));
    return *reinterpret_cast<uint32_t*>(&p);
}

// window-order row -> original token index
__device__ __forceinline__ int map_row(int r) {
    int win = r / NWN, n = r % NWN;
    int b = win >> 4, wIdx = win & 15;
    int hs = (wIdx >> 2) * 7 + n / 7;
    int ws = (wIdx & 3) * 7 + n % 7;
    int h = hs + 3; if (h >= 28) h -= 28;
    int w = ws + 3; if (w >= 28) w -= 28;
    return b * 784 + h * 28 + w;
}

// ---------------- merged setup: weight transpose-casts + bias prescale + bias/mask table ----
__global__ __launch_bounds__(256)
void cvt_all(const float* __restrict__ qkv_w, const float* __restrict__ proj_w,
             const float* __restrict__ fc1_w, const float* __restrict__ fc2_w,
             const float* __restrict__ qkv_b, const float* __restrict__ rpb) {
    const int t = blockIdx.x;
    const int tid = threadIdx.x;

    if (t >= 1728) {                         // table part
        const int b = t - 1728;              // 0..191 = wcls*12 + head
        const int wIdx = b / 12, head = b % 12;
        for (int i = tid; i < 4096; i += 256) {
            int r = i >> 6, c = i & 63;
            float v = -1e30f;
            if (r < NWN && c < NWN) {
                int rh = r / 7, rw = r % 7, chh = c / 7, cww = c % 7;
                int di = rh - chh + 6, dj = rw - cww + 6;
                v = rpb[(di * 13 + dj) * HEADS + head];
                int hh_r = (wIdx >> 2) * 7 + rh, ww_r = (wIdx & 3) * 7 + rw;
                int hh_c = (wIdx >> 2) * 7 + chh, ww_c = (wIdx & 3) * 7 + cww;
                int clr = (hh_r < 21 ? 0 : (hh_r < 25 ? 1 : 2)) * 3 + (ww_r < 21 ? 0 : (ww_r < 25 ? 1 : 2));
                int clc = (hh_c < 21 ? 0 : (hh_c < 25 ? 1 : 2)) * 3 + (ww_c < 21 ? 0 : (ww_c < 25 ? 1 : 2));
                if (clr != clc) v -= 100.f;
            }
            g_tbl[((size_t)b << 12) + i] = __float2bfloat16(v);
        }
        return;
    }

    __shared__ float tile[32][33];
    const int tx = tid & 31, ty = tid >> 5;

    if (t < 5) {
        int idx = t * 256 + tid;
        if (idx < 3 * DIM)
            g_bqkv[idx] = qkv_b[idx] * (idx < DIM ? QSCALE : 1.f);
    }

    const float* src; __nv_bfloat16* dst;
    int K, N, tn, tk;
    float scale0 = 1.f;
    if (t < 432)       { src = qkv_w;  dst = g_wqkv;  K = 384;  N = 1152; tn = t % 36;          tk = t / 36;          scale0 = QSCALE; }
    else if (t < 576)  { src = proj_w; dst = g_wproj; K = 384;  N = 384;  tn = (t - 432) % 12;  tk = (t - 432) / 12; }
    else if (t < 1152) { src = fc1_w;  dst = g_wfc1;  K = 384;  N = 1536; tn = (t - 576) % 48;  tk = (t - 576) / 48; }
    else               { src = fc2_w;  dst = g_wfc2;  K = 1536; N = 384;  tn = (t - 1152) % 12; tk = (t - 1152) / 12; }

    int k0 = tk * 32, n0 = tn * 32;
#pragma unroll
    for (int i = 0; i < 4; i++)
        tile[ty + i * 8][tx] = src[(size_t)(k0 + ty + i * 8) * N + n0 + tx];
    __syncthreads();
#pragma unroll
    for (int i = 0; i < 4; i++) {
        int n = n0 + ty + i * 8;
        float s = (n < 384) ? scale0 : 1.f;
        dst[(size_t)n * K + k0 + tx] = __float2bfloat16(tile[tx][ty + i * 8] * s);
    }
}

// ---------------- LayerNorm: one warp per row, no smem, no syncthreads ----------------
template<bool PERM>
__global__ __launch_bounds__(256)
void ln_kernel(const float* __restrict__ in,
               const float* __restrict__ gamma,
               const float* __restrict__ beta,
               __nv_bfloat16* __restrict__ out) {
    const int wid = threadIdx.x >> 5, lane = threadIdx.x & 31;
    const int r = blockIdx.x * 8 + wid;
    const int src = PERM ? map_row(r) : r;
    const float* row = in + (size_t)src * DIM;

    float4 v[3];
    float s = 0.f, s2 = 0.f;
#pragma unroll
    for (int i = 0; i < 3; i++) {
        v[i] = *reinterpret_cast<const float4*>(&row[lane * 4 + i * 128]);
        s  += v[i].x + v[i].y + v[i].z + v[i].w;
        s2 += v[i].x * v[i].x + v[i].y * v[i].y + v[i].z * v[i].z + v[i].w * v[i].w;
    }
#pragma unroll
    for (int o = 16; o; o >>= 1) {
        s  += __shfl_xor_sync(0xffffffffu, s,  o);
        s2 += __shfl_xor_sync(0xffffffffu, s2, o);
    }
    float mean = s * (1.f / DIM);
    float rstd = rsqrtf(s2 * (1.f / DIM) - mean * mean + 1e-5f);

#pragma unroll
    for (int i = 0; i < 3; i++) {
        int c = lane * 4 + i * 128;
        float4 g = *reinterpret_cast<const float4*>(&gamma[c]);
        float4 b = *reinterpret_cast<const float4*>(&beta[c]);
        float o0 = (v[i].x - mean) * rstd * g.x + b.x;
        float o1 = (v[i].y - mean) * rstd * g.y + b.y;
        float o2 = (v[i].z - mean) * rstd * g.z + b.z;
        float o3 = (v[i].w - mean) * rstd * g.w + b.w;
        uint2 pk = make_uint2(pack_bf16(o0, o1), pack_bf16(o2, o3));
        *reinterpret_cast<uint2*>(&out[(size_t)r * DIM + c]) = pk;
    }
}

// ---------------- mma.sync GEMM: 128x128x32 CTA tile, 8 warps of 32x64, 4 stages ----------------
#define STAGE_B 16384
#define NSTAGE  4
#define GEMM_SMEM (NSTAGE * STAGE_B)

template<int MODE>
__global__ __launch_bounds__(256, 2)
void mma_gemm(const __nv_bfloat16* __restrict__ A,
              const __nv_bfloat16* __restrict__ B,
              const float* __restrict__ bias,
              const float* __restrict__ resid,
              __nv_bfloat16* __restrict__ outb,
              float* __restrict__ outf,
              int N, int K) {
    extern __shared__ __align__(1024) char smem[];   // per stage: A 8KB | B 8KB
    const uint32_t sbase = smem_u32(smem);

    const int tid = threadIdx.x;
    const int wid = tid >> 5, lane = tid & 31;
    const int warpM = wid >> 1;
    const int warpN = wid & 1;
    const int m0 = blockIdx.y * 128, n0 = blockIdx.x * 128;

    float acc[2][8][4];
#pragma unroll
    for (int i = 0; i < 2; i++)
#pragma unroll
        for (int j = 0; j < 8; j++)
#pragma unroll
            for (int q = 0; q < 4; q++) acc[i][j][q] = 0.f;

    const int nch = K >> 5;
    const int lr = tid >> 2;
    const int lc = tid & 3;
    auto load_stage = [&](int s, int c) {
        uint32_t st = sbase + s * STAGE_B;
        int k0 = c * 32;
#pragma unroll
        for (int i = 0; i < 2; i++) {
            int r = lr + i * 64;
            uint32_t sw = (uint32_t)((lc ^ ((r >> 1) & 3)) << 4);
            CP_ASYNC16(st + r * 64 + sw, A + (size_t)(m0 + r) * K + k0 + lc * 8);
        }
#pragma unroll
        for (int i = 0; i < 2; i++) {
            int r = lr + i * 64;
            uint32_t sw = (uint32_t)((lc ^ ((r >> 1) & 3)) << 4);
            CP_ASYNC16(st + 8192 + r * 64 + sw, B + (size_t)(n0 + r) * K + k0 + lc * 8);
        }
        CP_COMMIT();
    };

    load_stage(0, 0);
    if (nch > 1) load_stage(1, 1);
    if (nch > 2) load_stage(2, 2);

    const int lrow = lane & 15;
    const int lhalf = lane >> 4;

    for (int c = 0; c < nch; c++) {
        if (c + 2 < nch)      asm volatile("cp.async.wait_group 2;" ::: "memory");
        else if (c + 1 < nch) asm volatile("cp.async.wait_group 1;" ::: "memory");
        else                  asm volatile("cp.async.wait_group 0;" ::: "memory");
        __syncthreads();
        if (c + 3 < nch) load_stage((c + 3) & 3, c + 3);

        uint32_t sA = sbase + (c & 3) * STAGE_B;
        uint32_t sB = sA + 8192;

        uint32_t a[2][2][4];
#pragma unroll
        for (int kh = 0; kh < 2; kh++)
#pragma unroll
            for (int mt = 0; mt < 2; mt++) {
                int r = warpM * 32 + mt * 16 + lrow;
                int chunk = kh * 2 + lhalf;
                ldmatrix_x4(a[kh][mt], sA + r * 64 + (uint32_t)((chunk ^ ((r >> 1) & 3)) << 4));
            }
#pragma unroll
        for (int kh = 0; kh < 2; kh++) {
            int chunk = kh * 2 + lhalf;
#pragma unroll
            for (int np = 0; np < 4; np++) {
                uint32_t b[4];
                int r = warpN * 64 + np * 16 + lrow;
                ldmatrix_x4(b, sB + r * 64 + (uint32_t)((chunk ^ ((r >> 1) & 3)) << 4));
#pragma unroll
                for (int mt = 0; mt < 2; mt++) {
                    mma_16816(acc[mt][2 * np],     a[kh][mt], b[0], b[2]);
                    mma_16816(acc[mt][2 * np + 1], a[kh][mt], b[1], b[3]);
                }
            }
        }
    }

    // ---------------- fused epilogue on register accumulators ----------------
    const int colq = (lane & 3) * 2;
#pragma unroll
    for (int mt = 0; mt < 2; mt++) {
        int grow0 = m0 + warpM * 32 + mt * 16 + (lane >> 2);
        int grow1 = grow0 + 8;
        int dst0 = (MODE == 1) ? map_row(grow0) : grow0;
        int dst1 = (MODE == 1) ? map_row(grow1) : grow1;
#pragma unroll
        for (int nt = 0; nt < 8; nt++) {
            int gc = n0 + warpN * 64 + nt * 8 + colq;
            float b0 = bias[gc], b1 = bias[gc + 1];
            float v00 = acc[mt][nt][0] + b0, v01 = acc[mt][nt][1] + b1;
            float v10 = acc[mt][nt][2] + b0, v11 = acc[mt][nt][3] + b1;
            if (MODE == 0) {
                *reinterpret_cast<__nv_bfloat162*>(&outb[(size_t)grow0 * N + gc]) =
                    __nv_bfloat162(__float2bfloat16(v00), __float2bfloat16(v01));
                *reinterpret_cast<__nv_bfloat162*>(&outb[(size_t)grow1 * N + gc]) =
                    __nv_bfloat162(__float2bfloat16(v10), __float2bfloat16(v11));
            } else if (MODE == 1) {
                const float2 r0 = *reinterpret_cast<const float2*>(&resid[(size_t)dst0 * N + gc]);
                const float2 r1 = *reinterpret_cast<const float2*>(&resid[(size_t)dst1 * N + gc]);
                *reinterpret_cast<float2*>(&outf[(size_t)dst0 * N + gc]) =
                    make_float2(v00 + r0.x, v01 + r0.y);
                *reinterpret_cast<float2*>(&outf[(size_t)dst1 * N + gc]) =
                    make_float2(v10 + r1.x, v11 + r1.y);
            } else if (MODE == 2) {
                v00 = 0.5f * v00 * (1.0f + erff(v00 * 0.7071067811865475f));
                v01 = 0.5f * v01 * (1.0f + erff(v01 * 0.7071067811865475f));
                v10 = 0.5f * v10 * (1.0f + erff(v10 * 0.7071067811865475f));
                v11 = 0.5f * v11 * (1.0f + erff(v11 * 0.7071067811865475f));
                *reinterpret_cast<__nv_bfloat162*>(&outb[(size_t)grow0 * N + gc]) =
                    __nv_bfloat162(__float2bfloat16(v00), __float2bfloat16(v01));
                *reinterpret_cast<__nv_bfloat162*>(&outb[(size_t)grow1 * N + gc]) =
                    __nv_bfloat162(__float2bfloat16(v10), __float2bfloat16(v11));
            } else {
                const float2 r0 = *reinterpret_cast<const float2*>(&resid[(size_t)grow0 * N + gc]);
                const float2 r1 = *reinterpret_cast<const float2*>(&resid[(size_t)grow1 * N + gc]);
                *reinterpret_cast<float2*>(&outf[(size_t)grow0 * N + gc]) =
                    make_float2(v00 + r0.x, v01 + r0.y);
                *reinterpret_cast<float2*>(&outf[(size_t)grow1 * N + gc]) =
                    make_float2(v10 + r1.x, v11 + r1.y);
            }
        }
    }
}

// ---------------- tensor-core windowed attention: block = (2 windows, head) ----------------
#define TBL_STRIDE 144    // bytes per table row in smem (conflict-free reads)
__global__ __launch_bounds__(256)
void attn_mma(const __nv_bfloat16* __restrict__ qkv,
              const __nv_bfloat16* __restrict__ tbl,
              __nv_bfloat16* __restrict__ out) {
    __shared__ __align__(1024) char sq[2][4096];
    __shared__ __align__(1024) char sk[2][4096];
    __shared__ __align__(1024) char sv[2][4096];
    __shared__ __align__(16)   char stbl[64 * TBL_STRIDE];

    const int tid = threadIdx.x;
    const int sub = tid >> 7;                 // 0/1 half-block
    const int t2 = tid & 127;
    const int lane = tid & 31, w4 = (tid >> 5) & 3;
    const int win = blockIdx.x + sub * 512;
    const int head = blockIdx.y;
    const uint32_t qb = smem_u32(sq[sub]), kb = smem_u32(sk[sub]), vb = smem_u32(sv[sub]);
    const uint32_t tbase = smem_u32(stbl);

    // stage the shared table slice (8KB) once for both windows (cp.async)
    {
        const char* g = reinterpret_cast<const char*>(
            tbl + (((size_t)((blockIdx.x & 15) * 12 + head)) << 12));
#pragma unroll
        for (int i = tid; i < 512; i += 256) {
            int r = i >> 3, c16 = i & 7;
            CP_ASYNC16(tbase + r * TBL_STRIDE + c16 * 16, g + i * 16);
        }
    }

    // stage q/k/v via cp.async with zero-fill for padding rows
    const char* basep = reinterpret_cast<const char*>(qkv + (size_t)win * NWN * 1152 + head * HD);
#pragma unroll
    for (int i = t2; i < 256; i += 128) {
        int r = i >> 2, c = i & 3;
        int n = (r < NWN) ? 16 : 0;
        const char* p = basep + (size_t)r * 2304;       // 1152 bf16 = 2304 B per token
        uint32_t sw = (uint32_t)((c ^ ((r >> 1) & 3)) << 4);
        CP_ASYNC16_Z(qb + r * 64 + sw, p + c * 16, n);
        CP_ASYNC16_Z(kb + r * 64 + sw, p + 768 + c * 16, n);
        CP_ASYNC16_Z(vb + r * 64 + sw, p + 1536 + c * 16, n);
    }
    CP_COMMIT();
    CP_WAIT0();
    __syncthreads();

    const int lrow = lane & 15, lhalf = lane >> 4;

    // ---- S = q k^T (16x64 per warp) ----
    float sacc[8][4];
#pragma unroll
    for (int t = 0; t < 8; t++)
#pragma unroll
        for (int q = 0; q < 4; q++) sacc[t][q] = 0.f;

    uint32_t af[2][4];
#pragma unroll
    for (int kh = 0; kh < 2; kh++) {
        int r = w4 * 16 + lrow;
        int chunk = kh * 2 + lhalf;
        ldmatrix_x4(af[kh], qb + r * 64 + (uint32_t)((chunk ^ ((r >> 1) & 3)) << 4));
    }
#pragma unroll
    for (int kh = 0; kh < 2; kh++) {
        int chunk = kh * 2 + lhalf;
        uint32_t b[4][4];
#pragma unroll
        for (int np = 0; np < 4; np++) {
            int r = np * 16 + lrow;
            ldmatrix_x4(b[np], kb + r * 64 + (uint32_t)((chunk ^ ((r >> 1) & 3)) << 4));
        }
#pragma unroll
        for (int np = 0; np < 4; np++) {
            mma_16816(sacc[2 * np],     af[kh], b[np][0], b[np][2]);
            mma_16816(sacc[2 * np + 1], af[kh], b[np][1], b[np][3]);
        }
    }

    // ---- bias + mask from smem-staged bf16 table (conflict-free) ----
    const int r0 = w4 * 16 + (lane >> 2), r1 = r0 + 8;
    const int c0 = 2 * (lane & 3);
    const uint32_t tb0 = tbase + r0 * TBL_STRIDE + c0 * 2;
#pragma unroll
    for (int t = 0; t < 8; t++) {
        uint32_t u0, u1;
        asm volatile("ld.shared.b32 %0, [%1];" : "=r"(u0) : "r"(tb0 + 16 * t));
        asm volatile("ld.shared.b32 %0, [%1];" : "=r"(u1) : "r"(tb0 + 8 * TBL_STRIDE + 16 * t));
        float2 b0 = __bfloat1622float2(*reinterpret_cast<__nv_bfloat162*>(&u0));
        float2 b1 = __bfloat1622float2(*reinterpret_cast<__nv_bfloat162*>(&u1));
        sacc[t][0] += b0.x; sacc[t][1] += b0.y;
        sacc[t][2] += b1.x; sacc[t][3] += b1.y;
    }

    // ---- softmax on registers ----
    float mx0 = -1e30f, mx1 = -1e30f;
#pragma unroll
    for (int t = 0; t < 8; t++) {
        mx0 = fmaxf(mx0, fmaxf(sacc[t][0], sacc[t][1]));
        mx1 = fmaxf(mx1, fmaxf(sacc[t][2], sacc[t][3]));
    }
    mx0 = fmaxf(mx0, __shfl_xor_sync(0xffffffffu, mx0, 1));
    mx0 = fmaxf(mx0, __shfl_xor_sync(0xffffffffu, mx0, 2));
    mx1 = fmaxf(mx1, __shfl_xor_sync(0xffffffffu, mx1, 1));
    mx1 = fmaxf(mx1, __shfl_xor_sync(0xffffffffu, mx1, 2));
    float s0 = 0.f, s1 = 0.f;
#pragma unroll
    for (int t = 0; t < 8; t++) {
        float e0 = __expf(sacc[t][0] - mx0); sacc[t][0] = e0; s0 += e0;
        float e1 = __expf(sacc[t][1] - mx0); sacc[t][1] = e1; s0 += e1;
        float e2 = __expf(sacc[t][2] - mx1); sacc[t][2] = e2; s1 += e2;
        float e3 = __expf(sacc[t][3] - mx1); sacc[t][3] = e3; s1 += e3;
    }
    s0 += __shfl_xor_sync(0xffffffffu, s0, 1);
    s0 += __shfl_xor_sync(0xffffffffu, s0, 2);
    s1 += __shfl_xor_sync(0xffffffffu, s1, 1);
    s1 += __shfl_xor_sync(0xffffffffu, s1, 2);
    float inv0 = 1.f / s0, inv1 = 1.f / s1;
#pragma unroll
    for (int t = 0; t < 8; t++) {
        sacc[t][0] *= inv0; sacc[t][1] *= inv0;
        sacc[t][2] *= inv1; sacc[t][3] *= inv1;
    }

    // ---- out = P V : P repacked as A frags; V natural layout via ldmatrix.trans ----
    float oacc[4][4];
#pragma unroll
    for (int t = 0; t < 4; t++)
#pragma unroll
        for (int q = 0; q < 4; q++) oacc[t][q] = 0.f;

#pragma unroll
    for (int j = 0; j < 4; j++) {
        uint32_t pa[4];
        pa[0] = pack_bf16(sacc[2 * j][0],     sacc[2 * j][1]);
        pa[1] = pack_bf16(sacc[2 * j][2],     sacc[2 * j][3]);
        pa[2] = pack_bf16(sacc[2 * j + 1][0], sacc[2 * j + 1][1]);
        pa[3] = pack_bf16(sacc[2 * j + 1][2], sacc[2 * j + 1][3]);
        int vr = j * 16 + ((lane >> 3) & 1) * 8 + (lane & 7);
        uint32_t t4[2][4];
#pragma unroll
        for (int dblk = 0; dblk < 2; dblk++) {
            int chunk = dblk * 2 + (lane >> 4);
            ldmatrix_x4_trans(t4[dblk], vb + vr * 64 + (uint32_t)((chunk ^ ((vr >> 1) & 3)) << 4));
        }
#pragma unroll
        for (int dblk = 0; dblk < 2; dblk++) {
            mma_16816(oacc[2 * dblk],     pa, t4[dblk][0], t4[dblk][1]);
            mma_16816(oacc[2 * dblk + 1], pa, t4[dblk][2], t4[dblk][3]);
        }
    }

    if (r0 < NWN) {
        size_t ob = ((size_t)win * NWN + r0) * DIM + head * HD;
#pragma unroll
        for (int t = 0; t < 4; t++) {
            int d = 8 * t + c0;
            *reinterpret_cast<__nv_bfloat162*>(&out[ob + d]) =
                __nv_bfloat162(__float2bfloat16(oacc[t][0]), __float2bfloat16(oacc[t][1]));
        }
    }
    if (r1 < NWN) {
        size_t ob = ((size_t)win * NWN + r1) * DIM + head * HD;
#pragma unroll
        for (int t = 0; t < 4; t++) {
            int d = 8 * t + c0;
            *reinterpret_cast<__nv_bfloat162*>(&out[ob + d]) =
                __nv_bfloat162(__float2bfloat16(oacc[t][2]), __float2bfloat16(oacc[t][3]));
        }
    }
}

// ---------------- launch ----------------
extern "C" void kernel_launch(void* const* d_in, const int* in_sizes, int n_in,
                              void* d_out, int out_size) {
    const float* x      = (const float*)d_in[0];
    const float* n1g    = (const float*)d_in[1];
    const float* n1b    = (const float*)d_in[2];
    const float* qkv_w  = (const float*)d_in[3];
    const float* qkv_b  = (const float*)d_in[4];
    const float* proj_w = (const float*)d_in[5];
    const float* proj_b = (const float*)d_in[6];
    const float* rpb    = (const float*)d_in[7];
    const float* n2g    = (const float*)d_in[8];
    const float* n2b    = (const float*)d_in[9];
    const float* fc1_w  = (const float*)d_in[10];
    const float* fc1_b  = (const float*)d_in[11];
    const float* fc2_w  = (const float*)d_in[12];
    const float* fc2_b  = (const float*)d_in[13];
    float* out = (float*)d_out;

    __nv_bfloat16 *xw, *qkv, *att, *m, *h1, *wqkv, *wproj, *wfc1, *wfc2, *tbl;
    float *y, *bqkv;
    cudaGetSymbolAddress((void**)&xw,    g_xw);
    cudaGetSymbolAddress((void**)&qkv,   g_qkv);
    cudaGetSymbolAddress((void**)&att,   g_att);
    cudaGetSymbolAddress((void**)&y,     g_y);
    cudaGetSymbolAddress((void**)&m,     g_m);
    cudaGetSymbolAddress((void**)&h1,    g_h1);
    cudaGetSymbolAddress((void**)&wqkv,  g_wqkv);
    cudaGetSymbolAddress((void**)&wproj, g_wproj);
    cudaGetSymbolAddress((void**)&wfc1,  g_wfc1);
    cudaGetSymbolAddress((void**)&wfc2,  g_wfc2);
    cudaGetSymbolAddress((void**)&bqkv,  g_bqkv);
    cudaGetSymbolAddress((void**)&tbl,   g_tbl);

    cudaFuncSetAttribute(mma_gemm<0>, cudaFuncAttributeMaxDynamicSharedMemorySize, GEMM_SMEM);
    cudaFuncSetAttribute(mma_gemm<1>, cudaFuncAttributeMaxDynamicSharedMemorySize, GEMM_SMEM);
    cudaFuncSetAttribute(mma_gemm<2>, cudaFuncAttributeMaxDynamicSharedMemorySize, GEMM_SMEM);
    cudaFuncSetAttribute(mma_gemm<3>, cudaFuncAttributeMaxDynamicSharedMemorySize, GEMM_SMEM);

    // side stream + events, created once on the (uncaptured) correctness call
    static cudaStream_t s1 = nullptr;
    static cudaEvent_t evFork = nullptr, evJoin = nullptr;
    if (!s1) {
        cudaStreamCreateWithFlags(&s1, cudaStreamNonBlocking);
        cudaEventCreateWithFlags(&evFork, cudaEventDisableTiming);
        cudaEventCreateWithFlags(&evJoin, cudaEventDisableTiming);
    }

    // fork: cvt_all (weights/table, independent of x) runs concurrently with LN1
    cudaEventRecord(evFork, 0);
    cudaStreamWaitEvent(s1, evFork, 0);
    cvt_all<<<1920, 256, 0, s1>>>(qkv_w, proj_w, fc1_w, fc2_w, qkv_b, rpb);
    cudaEventRecord(evJoin, s1);

    // LN1 + shift + window partition (warp per row) on main stream
    ln_kernel<true><<<NTOK / 8, 256>>>(x, n1g, n1b, xw);

    // join before QKV (needs weights)
    cudaStreamWaitEvent(0, evJoin, 0);

    // QKV (q-scale folded into weights/bias)
    mma_gemm<0><<<dim3(9, 392), 256, GEMM_SMEM>>>(xw, wqkv, bqkv, nullptr, qkv, nullptr, 3 * DIM, DIM);

    // attention (tensor cores; 2 windows/block, cp.async staging, smem table)
    attn_mma<<<dim3(512, HEADS), 256>>>(qkv, tbl, att);

    // proj + window reverse + unshift + residual
    mma_gemm<1><<<dim3(3, 392), 256, GEMM_SMEM>>>(att, wproj, proj_b, x, nullptr, y, DIM, DIM);

    // LN2
    ln_kernel<false><<<NTOK / 8, 256>>>(y, n2g, n2b, m);

    // FC1 + GELU
    mma_gemm<2><<<dim3(12, 392), 256, GEMM_SMEM>>>(m, wfc1, fc1_b, nullptr, h1, nullptr, 4 * DIM, DIM);

    // FC2 + residual -> output
    mma_gemm<3><<<dim3(3, 392), 256, GEMM_SMEM>>>(h1, wfc2, fc2_b, y, nullptr, out, DIM, 4 * DIM);
}

// round 14
// speedup vs baseline: 1.0111x; 1.0012x over previous
#include <cuda_runtime.h>
#include <cuda_bf16.h>
#include <cstdint>

#define DIM    384
#define NTOK   50176      // 1024 windows * 49 tokens
#define NWIN   1024
#define HEADS  12
#define HD     32
#define NWN    49
#define QSCALE 0.17677669529663689f  // 1/sqrt(32)

// ---------------- scratch (static device memory, no allocs) ----------------
__device__ __nv_bfloat16 g_xw [(size_t)NTOK * DIM];
__device__ __nv_bfloat16 g_qkv[(size_t)NTOK * 3 * DIM];
__device__ __nv_bfloat16 g_att[(size_t)NTOK * DIM];
__device__ float         g_y  [(size_t)NTOK * DIM];
__device__ __nv_bfloat16 g_m  [(size_t)NTOK * DIM];
__device__ __nv_bfloat16 g_h1 [(size_t)NTOK * 4 * DIM];
// weights stored TRANSPOSED: [N, K] K-major bf16
__device__ __nv_bfloat16 g_wqkv [3 * DIM * DIM];
__device__ __nv_bfloat16 g_wproj[DIM * DIM];
__device__ __nv_bfloat16 g_wfc1 [4 * DIM * DIM];
__device__ __nv_bfloat16 g_wfc2 [DIM * 4 * DIM];
__device__ float         g_bqkv [3 * DIM];              // q-prescaled qkv bias
__device__ __nv_bfloat16 g_tbl  [192 * 4096];           // bias+mask (bf16): [wcls][head][64][64]

// ---------------- helpers ----------------
__device__ __forceinline__ uint32_t smem_u32(const void* p) {
    uint32_t a;
    asm("{ .reg .u64 t; cvta.to.shared.u64 t, %1; cvt.u32.u64 %0, t; }" : "=r"(a) : "l"(p));
    return a;
}

#define CP_ASYNC16(dst, src) \
    asm volatile("cp.async.cg.shared.global [%0], [%1], 16;" :: "r"(dst), "l"(src) : "memory")
#define CP_ASYNC16_Z(dst, src, n) \
    asm volatile("cp.async.cg.shared.global [%0], [%1], 16, %2;" :: "r"(dst), "l"(src), "r"(n) : "memory")
#define CP_COMMIT() asm volatile("cp.async.commit_group;" ::: "memory")
#define CP_WAIT0()  asm volatile("cp.async.wait_group 0;" ::: "memory")
#define CP_WAIT1()  asm volatile("cp.async.wait_group 1;" ::: "memory")

__device__ __forceinline__ void ldmatrix_x4(uint32_t* r, uint32_t addr) {
    asm volatile("ldmatrix.sync.aligned.m8n8.x4.shared.b16 {%0,%1,%2,%3}, [%4];"
                 : "=r"(r[0]), "=r"(r[1]), "=r"(r[2]), "=r"(r[3]) : "r"(addr));
}
__device__ __forceinline__ void ldmatrix_x4_trans(uint32_t* r, uint32_t addr) {
    asm volatile("ldmatrix.sync.aligned.m8n8.x4.trans.shared.b16 {%0,%1,%2,%3}, [%4];"
                 : "=r"(r[0]), "=r"(r[1]), "=r"(r[2]), "=r"(r[3]) : "r"(addr));
}

__device__ __forceinline__ void mma_16816(float* c, const uint32_t* a, uint32_t b0, uint32_t b1) {
    asm volatile(
        "mma.sync.aligned.m16n8k16.row.col.f32.bf16.bf16.f32 "
        "{%0,%1,%2,%3}, {%4,%5,%6,%7}, {%8,%9}, {%0,%1,%2,%3};"
        : "+f"(c[0]), "+f"(c[1]), "+f"(c[2]), "+f"(c[3])
        : "r"(a[0]), "r"(a[1]), "r"(a[2]), "r"(a[3]), "r"(b0), "r"(b1));
}

__device__ __forceinline__ uint32_t pack_bf16(float lo, float hi) {
    __nv_bfloat162 p = __float22bfloat162_rn(make_float2(lo, hi));
    return *reinterpret_cast<uint32_t*>(&p);
}

// window-order row -> original token index
__device__ __forceinline__ int map_row(int r) {
    int win = r / NWN, n = r % NWN;
    int b = win >> 4, wIdx = win & 15;
    int hs = (wIdx >> 2) * 7 + n / 7;
    int ws = (wIdx & 3) * 7 + n % 7;
    int h = hs + 3; if (h >= 28) h -= 28;
    int w = ws + 3; if (w >= 28) w -= 28;
    return b * 784 + h * 28 + w;
}

// ---------------- merged setup: weight transpose-casts + bias prescale + bias/mask table ----
__global__ __launch_bounds__(256)
void cvt_all(const float* __restrict__ qkv_w, const float* __restrict__ proj_w,
             const float* __restrict__ fc1_w, const float* __restrict__ fc2_w,
             const float* __restrict__ qkv_b, const float* __restrict__ rpb) {
    const int t = blockIdx.x;
    const int tid = threadIdx.x;

    if (t >= 1728) {                         // table part
        const int b = t - 1728;              // 0..191 = wcls*12 + head
        const int wIdx = b / 12, head = b % 12;
        for (int i = tid; i < 4096; i += 256) {
            int r = i >> 6, c = i & 63;
            float v = -1e30f;
            if (r < NWN && c < NWN) {
                int rh = r / 7, rw = r % 7, chh = c / 7, cww = c % 7;
                int di = rh - chh + 6, dj = rw - cww + 6;
                v = rpb[(di * 13 + dj) * HEADS + head];
                int hh_r = (wIdx >> 2) * 7 + rh, ww_r = (wIdx & 3) * 7 + rw;
                int hh_c = (wIdx >> 2) * 7 + chh, ww_c = (wIdx & 3) * 7 + cww;
                int clr = (hh_r < 21 ? 0 : (hh_r < 25 ? 1 : 2)) * 3 + (ww_r < 21 ? 0 : (ww_r < 25 ? 1 : 2));
                int clc = (hh_c < 21 ? 0 : (hh_c < 25 ? 1 : 2)) * 3 + (ww_c < 21 ? 0 : (ww_c < 25 ? 1 : 2));
                if (clr != clc) v -= 100.f;
            }
            g_tbl[((size_t)b << 12) + i] = __float2bfloat16(v);
        }
        return;
    }

    __shared__ float tile[32][33];
    const int tx = tid & 31, ty = tid >> 5;

    if (t < 5) {
        int idx = t * 256 + tid;
        if (idx < 3 * DIM)
            g_bqkv[idx] = qkv_b[idx] * (idx < DIM ? QSCALE : 1.f);
    }

    const float* src; __nv_bfloat16* dst;
    int K, N, tn, tk;
    float scale0 = 1.f;
    if (t < 432)       { src = qkv_w;  dst = g_wqkv;  K = 384;  N = 1152; tn = t % 36;          tk = t / 36;          scale0 = QSCALE; }
    else if (t < 576)  { src = proj_w; dst = g_wproj; K = 384;  N = 384;  tn = (t - 432) % 12;  tk = (t - 432) / 12; }
    else if (t < 1152) { src = fc1_w;  dst = g_wfc1;  K = 384;  N = 1536; tn = (t - 576) % 48;  tk = (t - 576) / 48; }
    else               { src = fc2_w;  dst = g_wfc2;  K = 1536; N = 384;  tn = (t - 1152) % 12; tk = (t - 1152) / 12; }

    int k0 = tk * 32, n0 = tn * 32;
#pragma unroll
    for (int i = 0; i < 4; i++)
        tile[ty + i * 8][tx] = src[(size_t)(k0 + ty + i * 8) * N + n0 + tx];
    __syncthreads();
#pragma unroll
    for (int i = 0; i < 4; i++) {
        int n = n0 + ty + i * 8;
        float s = (n < 384) ? scale0 : 1.f;
        dst[(size_t)n * K + k0 + tx] = __float2bfloat16(tile[tx][ty + i * 8] * s);
    }
}

// ---------------- LayerNorm: one warp per row, no smem, no syncthreads ----------------
template<bool PERM>
__global__ __launch_bounds__(256)
void ln_kernel(const float* __restrict__ in,
               const float* __restrict__ gamma,
               const float* __restrict__ beta,
               __nv_bfloat16* __restrict__ out) {
    const int wid = threadIdx.x >> 5, lane = threadIdx.x & 31;
    const int r = blockIdx.x * 8 + wid;
    const int src = PERM ? map_row(r) : r;
    const float* row = in + (size_t)src * DIM;

    float4 v[3];
    float s = 0.f, s2 = 0.f;
#pragma unroll
    for (int i = 0; i < 3; i++) {
        v[i] = *reinterpret_cast<const float4*>(&row[lane * 4 + i * 128]);
        s  += v[i].x + v[i].y + v[i].z + v[i].w;
        s2 += v[i].x * v[i].x + v[i].y * v[i].y + v[i].z * v[i].z + v[i].w * v[i].w;
    }
#pragma unroll
    for (int o = 16; o; o >>= 1) {
        s  += __shfl_xor_sync(0xffffffffu, s,  o);
        s2 += __shfl_xor_sync(0xffffffffu, s2, o);
    }
    float mean = s * (1.f / DIM);
    float rstd = rsqrtf(s2 * (1.f / DIM) - mean * mean + 1e-5f);

#pragma unroll
    for (int i = 0; i < 3; i++) {
        int c = lane * 4 + i * 128;
        float4 g = *reinterpret_cast<const float4*>(&gamma[c]);
        float4 b = *reinterpret_cast<const float4*>(&beta[c]);
        float o0 = (v[i].x - mean) * rstd * g.x + b.x;
        float o1 = (v[i].y - mean) * rstd * g.y + b.y;
        float o2 = (v[i].z - mean) * rstd * g.z + b.z;
        float o3 = (v[i].w - mean) * rstd * g.w + b.w;
        uint2 pk = make_uint2(pack_bf16(o0, o1), pack_bf16(o2, o3));
        *reinterpret_cast<uint2*>(&out[(size_t)r * DIM + c]) = pk;
    }
}

// ---------------- mma.sync GEMM: 128x128x32 CTA tile, 8 warps of 32x64, 4 stages ----------------
#define STAGE_B 16384
#define NSTAGE  4
#define GEMM_SMEM (NSTAGE * STAGE_B)

template<int MODE>
__global__ __launch_bounds__(256, 2)
void mma_gemm(const __nv_bfloat16* __restrict__ A,
              const __nv_bfloat16* __restrict__ B,
              const float* __restrict__ bias,
              const float* __restrict__ resid,
              __nv_bfloat16* __restrict__ outb,
              float* __restrict__ outf,
              int N, int K) {
    extern __shared__ __align__(1024) char smem[];   // per stage: A 8KB | B 8KB
    const uint32_t sbase = smem_u32(smem);

    const int tid = threadIdx.x;
    const int wid = tid >> 5, lane = tid & 31;
    const int warpM = wid >> 1;
    const int warpN = wid & 1;
    const int m0 = blockIdx.y * 128, n0 = blockIdx.x * 128;

    float acc[2][8][4];
#pragma unroll
    for (int i = 0; i < 2; i++)
#pragma unroll
        for (int j = 0; j < 8; j++)
#pragma unroll
            for (int q = 0; q < 4; q++) acc[i][j][q] = 0.f;

    const int nch = K >> 5;
    const int lr = tid >> 2;
    const int lc = tid & 3;
    auto load_stage = [&](int s, int c) {
        uint32_t st = sbase + s * STAGE_B;
        int k0 = c * 32;
#pragma unroll
        for (int i = 0; i < 2; i++) {
            int r = lr + i * 64;
            uint32_t sw = (uint32_t)((lc ^ ((r >> 1) & 3)) << 4);
            CP_ASYNC16(st + r * 64 + sw, A + (size_t)(m0 + r) * K + k0 + lc * 8);
        }
#pragma unroll
        for (int i = 0; i < 2; i++) {
            int r = lr + i * 64;
            uint32_t sw = (uint32_t)((lc ^ ((r >> 1) & 3)) << 4);
            CP_ASYNC16(st + 8192 + r * 64 + sw, B + (size_t)(n0 + r) * K + k0 + lc * 8);
        }
        CP_COMMIT();
    };

    load_stage(0, 0);
    if (nch > 1) load_stage(1, 1);
    if (nch > 2) load_stage(2, 2);

    const int lrow = lane & 15;
    const int lhalf = lane >> 4;

    for (int c = 0; c < nch; c++) {
        if (c + 2 < nch)      asm volatile("cp.async.wait_group 2;" ::: "memory");
        else if (c + 1 < nch) asm volatile("cp.async.wait_group 1;" ::: "memory");
        else                  asm volatile("cp.async.wait_group 0;" ::: "memory");
        __syncthreads();
        if (c + 3 < nch) load_stage((c + 3) & 3, c + 3);

        uint32_t sA = sbase + (c & 3) * STAGE_B;
        uint32_t sB = sA + 8192;

        uint32_t a[2][2][4];
#pragma unroll
        for (int kh = 0; kh < 2; kh++)
#pragma unroll
            for (int mt = 0; mt < 2; mt++) {
                int r = warpM * 32 + mt * 16 + lrow;
                int chunk = kh * 2 + lhalf;
                ldmatrix_x4(a[kh][mt], sA + r * 64 + (uint32_t)((chunk ^ ((r >> 1) & 3)) << 4));
            }
#pragma unroll
        for (int kh = 0; kh < 2; kh++) {
            int chunk = kh * 2 + lhalf;
#pragma unroll
            for (int np = 0; np < 4; np++) {
                uint32_t b[4];
                int r = warpN * 64 + np * 16 + lrow;
                ldmatrix_x4(b, sB + r * 64 + (uint32_t)((chunk ^ ((r >> 1) & 3)) << 4));
#pragma unroll
                for (int mt = 0; mt < 2; mt++) {
                    mma_16816(acc[mt][2 * np],     a[kh][mt], b[0], b[2]);
                    mma_16816(acc[mt][2 * np + 1], a[kh][mt], b[1], b[3]);
                }
            }
        }
    }

    // ---------------- fused epilogue on register accumulators ----------------
    const int colq = (lane & 3) * 2;
#pragma unroll
    for (int mt = 0; mt < 2; mt++) {
        int grow0 = m0 + warpM * 32 + mt * 16 + (lane >> 2);
        int grow1 = grow0 + 8;
        int dst0 = (MODE == 1) ? map_row(grow0) : grow0;
        int dst1 = (MODE == 1) ? map_row(grow1) : grow1;
#pragma unroll
        for (int nt = 0; nt < 8; nt++) {
            int gc = n0 + warpN * 64 + nt * 8 + colq;
            float b0 = bias[gc], b1 = bias[gc + 1];
            float v00 = acc[mt][nt][0] + b0, v01 = acc[mt][nt][1] + b1;
            float v10 = acc[mt][nt][2] + b0, v11 = acc[mt][nt][3] + b1;
            if (MODE == 0) {
                *reinterpret_cast<__nv_bfloat162*>(&outb[(size_t)grow0 * N + gc]) =
                    __nv_bfloat162(__float2bfloat16(v00), __float2bfloat16(v01));
                *reinterpret_cast<__nv_bfloat162*>(&outb[(size_t)grow1 * N + gc]) =
                    __nv_bfloat162(__float2bfloat16(v10), __float2bfloat16(v11));
            } else if (MODE == 1) {
                const float2 r0 = *reinterpret_cast<const float2*>(&resid[(size_t)dst0 * N + gc]);
                const float2 r1 = *reinterpret_cast<const float2*>(&resid[(size_t)dst1 * N + gc]);
                *reinterpret_cast<float2*>(&outf[(size_t)dst0 * N + gc]) =
                    make_float2(v00 + r0.x, v01 + r0.y);
                *reinterpret_cast<float2*>(&outf[(size_t)dst1 * N + gc]) =
                    make_float2(v10 + r1.x, v11 + r1.y);
            } else if (MODE == 2) {
                v00 = 0.5f * v00 * (1.0f + erff(v00 * 0.7071067811865475f));
                v01 = 0.5f * v01 * (1.0f + erff(v01 * 0.7071067811865475f));
                v10 = 0.5f * v10 * (1.0f + erff(v10 * 0.7071067811865475f));
                v11 = 0.5f * v11 * (1.0f + erff(v11 * 0.7071067811865475f));
                *reinterpret_cast<__nv_bfloat162*>(&outb[(size_t)grow0 * N + gc]) =
                    __nv_bfloat162(__float2bfloat16(v00), __float2bfloat16(v01));
                *reinterpret_cast<__nv_bfloat162*>(&outb[(size_t)grow1 * N + gc]) =
                    __nv_bfloat162(__float2bfloat16(v10), __float2bfloat16(v11));
            } else {
                const float2 r0 = *reinterpret_cast<const float2*>(&resid[(size_t)grow0 * N + gc]);
                const float2 r1 = *reinterpret_cast<const float2*>(&resid[(size_t)grow1 * N + gc]);
                *reinterpret_cast<float2*>(&outf[(size_t)grow0 * N + gc]) =
                    make_float2(v00 + r0.x, v01 + r0.y);
                *reinterpret_cast<float2*>(&outf[(size_t)grow1 * N + gc]) =
                    make_float2(v10 + r1.x, v11 + r1.y);
            }
        }
    }
}

// ---------------- tensor-core windowed attention: block = (2 windows, head) ----------------
#define TBL_STRIDE 144    // bytes per table row in smem (conflict-free reads)
__global__ __launch_bounds__(256, 4)
void attn_mma(const __nv_bfloat16* __restrict__ qkv,
              const __nv_bfloat16* __restrict__ tbl,
              __nv_bfloat16* __restrict__ out) {
    __shared__ __align__(1024) char sq[2][4096];
    __shared__ __align__(1024) char sk[2][4096];
    __shared__ __align__(1024) char sv[2][4096];
    __shared__ __align__(16)   char stbl[64 * TBL_STRIDE];

    const int tid = threadIdx.x;
    const int sub = tid >> 7;                 // 0/1 half-block
    const int t2 = tid & 127;
    const int lane = tid & 31, w4 = (tid >> 5) & 3;
    const int win = blockIdx.x + sub * 512;
    const int head = blockIdx.y;
    const uint32_t qb = smem_u32(sq[sub]), kb = smem_u32(sk[sub]), vb = smem_u32(sv[sub]);
    const uint32_t tbase = smem_u32(stbl);

    // group 0: q/k/v staging (needed first)
    const char* basep = reinterpret_cast<const char*>(qkv + (size_t)win * NWN * 1152 + head * HD);
#pragma unroll
    for (int i = t2; i < 256; i += 128) {
        int r = i >> 2, c = i & 3;
        int n = (r < NWN) ? 16 : 0;
        const char* p = basep + (size_t)r * 2304;       // 1152 bf16 = 2304 B per token
        uint32_t sw = (uint32_t)((c ^ ((r >> 1) & 3)) << 4);
        CP_ASYNC16_Z(qb + r * 64 + sw, p + c * 16, n);
        CP_ASYNC16_Z(kb + r * 64 + sw, p + 768 + c * 16, n);
        CP_ASYNC16_Z(vb + r * 64 + sw, p + 1536 + c * 16, n);
    }
    CP_COMMIT();

    // group 1: table slice (only needed after S MMAs) — overlapped with S compute
    {
        const char* g = reinterpret_cast<const char*>(
            tbl + (((size_t)((blockIdx.x & 15) * 12 + head)) << 12));
#pragma unroll
        for (int i = tid; i < 512; i += 256) {
            int r = i >> 3, c16 = i & 7;
            CP_ASYNC16(tbase + r * TBL_STRIDE + c16 * 16, g + i * 16);
        }
    }
    CP_COMMIT();

    CP_WAIT1();           // q/k/v ready; table may still be in flight
    __syncthreads();

    const int lrow = lane & 15, lhalf = lane >> 4;

    // ---- S = q k^T (16x64 per warp) ----
    float sacc[8][4];
#pragma unroll
    for (int t = 0; t < 8; t++)
#pragma unroll
        for (int q = 0; q < 4; q++) sacc[t][q] = 0.f;

    uint32_t af[2][4];
#pragma unroll
    for (int kh = 0; kh < 2; kh++) {
        int r = w4 * 16 + lrow;
        int chunk = kh * 2 + lhalf;
        ldmatrix_x4(af[kh], qb + r * 64 + (uint32_t)((chunk ^ ((r >> 1) & 3)) << 4));
    }
#pragma unroll
    for (int kh = 0; kh < 2; kh++) {
        int chunk = kh * 2 + lhalf;
        uint32_t b[4][4];
#pragma unroll
        for (int np = 0; np < 4; np++) {
            int r = np * 16 + lrow;
            ldmatrix_x4(b[np], kb + r * 64 + (uint32_t)((chunk ^ ((r >> 1) & 3)) << 4));
        }
#pragma unroll
        for (int np = 0; np < 4; np++) {
            mma_16816(sacc[2 * np],     af[kh], b[np][0], b[np][2]);
            mma_16816(sacc[2 * np + 1], af[kh], b[np][1], b[np][3]);
        }
    }

    // table must be resident before the bias adds
    CP_WAIT0();
    __syncthreads();

    // ---- bias + mask from smem-staged bf16 table (conflict-free) ----
    const int r0 = w4 * 16 + (lane >> 2), r1 = r0 + 8;
    const int c0 = 2 * (lane & 3);
    const uint32_t tb0 = tbase + r0 * TBL_STRIDE + c0 * 2;
#pragma unroll
    for (int t = 0; t < 8; t++) {
        uint32_t u0, u1;
        asm volatile("ld.shared.b32 %0, [%1];" : "=r"(u0) : "r"(tb0 + 16 * t));
        asm volatile("ld.shared.b32 %0, [%1];" : "=r"(u1) : "r"(tb0 + 8 * TBL_STRIDE + 16 * t));
        float2 b0 = __bfloat1622float2(*reinterpret_cast<__nv_bfloat162*>(&u0));
        float2 b1 = __bfloat1622float2(*reinterpret_cast<__nv_bfloat162*>(&u1));
        sacc[t][0] += b0.x; sacc[t][1] += b0.y;
        sacc[t][2] += b1.x; sacc[t][3] += b1.y;
    }

    // ---- softmax on registers ----
    float mx0 = -1e30f, mx1 = -1e30f;
#pragma unroll
    for (int t = 0; t < 8; t++) {
        mx0 = fmaxf(mx0, fmaxf(sacc[t][0], sacc[t][1]));
        mx1 = fmaxf(mx1, fmaxf(sacc[t][2], sacc[t][3]));
    }
    mx0 = fmaxf(mx0, __shfl_xor_sync(0xffffffffu, mx0, 1));
    mx0 = fmaxf(mx0, __shfl_xor_sync(0xffffffffu, mx0, 2));
    mx1 = fmaxf(mx1, __shfl_xor_sync(0xffffffffu, mx1, 1));
    mx1 = fmaxf(mx1, __shfl_xor_sync(0xffffffffu, mx1, 2));
    float s0 = 0.f, s1 = 0.f;
#pragma unroll
    for (int t = 0; t < 8; t++) {
        float e0 = __expf(sacc[t][0] - mx0); sacc[t][0] = e0; s0 += e0;
        float e1 = __expf(sacc[t][1] - mx0); sacc[t][1] = e1; s0 += e1;
        float e2 = __expf(sacc[t][2] - mx1); sacc[t][2] = e2; s1 += e2;
        float e3 = __expf(sacc[t][3] - mx1); sacc[t][3] = e3; s1 += e3;
    }
    s0 += __shfl_xor_sync(0xffffffffu, s0, 1);
    s0 += __shfl_xor_sync(0xffffffffu, s0, 2);
    s1 += __shfl_xor_sync(0xffffffffu, s1, 1);
    s1 += __shfl_xor_sync(0xffffffffu, s1, 2);
    float inv0 = 1.f / s0, inv1 = 1.f / s1;
#pragma unroll
    for (int t = 0; t < 8; t++) {
        sacc[t][0] *= inv0; sacc[t][1] *= inv0;
        sacc[t][2] *= inv1; sacc[t][3] *= inv1;
    }

    // ---- out = P V : P repacked as A frags; V natural layout via ldmatrix.trans ----
    float oacc[4][4];
#pragma unroll
    for (int t = 0; t < 4; t++)
#pragma unroll
        for (int q = 0; q < 4; q++) oacc[t][q] = 0.f;

#pragma unroll
    for (int j = 0; j < 4; j++) {
        uint32_t pa[4];
        pa[0] = pack_bf16(sacc[2 * j][0],     sacc[2 * j][1]);
        pa[1] = pack_bf16(sacc[2 * j][2],     sacc[2 * j][3]);
        pa[2] = pack_bf16(sacc[2 * j + 1][0], sacc[2 * j + 1][1]);
        pa[3] = pack_bf16(sacc[2 * j + 1][2], sacc[2 * j + 1][3]);
        int vr = j * 16 + ((lane >> 3) & 1) * 8 + (lane & 7);
        uint32_t t4[2][4];
#pragma unroll
        for (int dblk = 0; dblk < 2; dblk++) {
            int chunk = dblk * 2 + (lane >> 4);
            ldmatrix_x4_trans(t4[dblk], vb + vr * 64 + (uint32_t)((chunk ^ ((vr >> 1) & 3)) << 4));
        }
#pragma unroll
        for (int dblk = 0; dblk < 2; dblk++) {
            mma_16816(oacc[2 * dblk],     pa, t4[dblk][0], t4[dblk][1]);
            mma_16816(oacc[2 * dblk + 1], pa, t4[dblk][2], t4[dblk][3]);
        }
    }

    if (r0 < NWN) {
        size_t ob = ((size_t)win * NWN + r0) * DIM + head * HD;
#pragma unroll
        for (int t = 0; t < 4; t++) {
            int d = 8 * t + c0;
            *reinterpret_cast<__nv_bfloat162*>(&out[ob + d]) =
                __nv_bfloat162(__float2bfloat16(oacc[t][0]), __float2bfloat16(oacc[t][1]));
        }
    }
    if (r1 < NWN) {
        size_t ob = ((size_t)win * NWN + r1) * DIM + head * HD;
#pragma unroll
        for (int t = 0; t < 4; t++) {
            int d = 8 * t + c0;
            *reinterpret_cast<__nv_bfloat162*>(&out[ob + d]) =
                __nv_bfloat162(__float2bfloat16(oacc[t][2]), __float2bfloat16(oacc[t][3]));
        }
    }
}

// ---------------- launch ----------------
extern "C" void kernel_launch(void* const* d_in, const int* in_sizes, int n_in,
                              void* d_out, int out_size) {
    const float* x      = (const float*)d_in[0];
    const float* n1g    = (const float*)d_in[1];
    const float* n1b    = (const float*)d_in[2];
    const float* qkv_w  = (const float*)d_in[3];
    const float* qkv_b  = (const float*)d_in[4];
    const float* proj_w = (const float*)d_in[5];
    const float* proj_b = (const float*)d_in[6];
    const float* rpb    = (const float*)d_in[7];
    const float* n2g    = (const float*)d_in[8];
    const float* n2b    = (const float*)d_in[9];
    const float* fc1_w  = (const float*)d_in[10];
    const float* fc1_b  = (const float*)d_in[11];
    const float* fc2_w  = (const float*)d_in[12];
    const float* fc2_b  = (const float*)d_in[13];
    float* out = (float*)d_out;

    __nv_bfloat16 *xw, *qkv, *att, *m, *h1, *wqkv, *wproj, *wfc1, *wfc2, *tbl;
    float *y, *bqkv;
    cudaGetSymbolAddress((void**)&xw,    g_xw);
    cudaGetSymbolAddress((void**)&qkv,   g_qkv);
    cudaGetSymbolAddress((void**)&att,   g_att);
    cudaGetSymbolAddress((void**)&y,     g_y);
    cudaGetSymbolAddress((void**)&m,     g_m);
    cudaGetSymbolAddress((void**)&h1,    g_h1);
    cudaGetSymbolAddress((void**)&wqkv,  g_wqkv);
    cudaGetSymbolAddress((void**)&wproj, g_wproj);
    cudaGetSymbolAddress((void**)&wfc1,  g_wfc1);
    cudaGetSymbolAddress((void**)&wfc2,  g_wfc2);
    cudaGetSymbolAddress((void**)&bqkv,  g_bqkv);
    cudaGetSymbolAddress((void**)&tbl,   g_tbl);

    cudaFuncSetAttribute(mma_gemm<0>, cudaFuncAttributeMaxDynamicSharedMemorySize, GEMM_SMEM);
    cudaFuncSetAttribute(mma_gemm<1>, cudaFuncAttributeMaxDynamicSharedMemorySize, GEMM_SMEM);
    cudaFuncSetAttribute(mma_gemm<2>, cudaFuncAttributeMaxDynamicSharedMemorySize, GEMM_SMEM);
    cudaFuncSetAttribute(mma_gemm<3>, cudaFuncAttributeMaxDynamicSharedMemorySize, GEMM_SMEM);

    // side stream + events, created once on the (uncaptured) correctness call
    static cudaStream_t s1 = nullptr;
    static cudaEvent_t evFork = nullptr, evJoin = nullptr;
    if (!s1) {
        cudaStreamCreateWithFlags(&s1, cudaStreamNonBlocking);
        cudaEventCreateWithFlags(&evFork, cudaEventDisableTiming);
        cudaEventCreateWithFlags(&evJoin, cudaEventDisableTiming);
    }

    // fork: cvt_all (weights/table, independent of x) runs concurrently with LN1
    cudaEventRecord(evFork, 0);
    cudaStreamWaitEvent(s1, evFork, 0);
    cvt_all<<<1920, 256, 0, s1>>>(qkv_w, proj_w, fc1_w, fc2_w, qkv_b, rpb);
    cudaEventRecord(evJoin, s1);

    // LN1 + shift + window partition (warp per row) on main stream
    ln_kernel<true><<<NTOK / 8, 256>>>(x, n1g, n1b, xw);

    // join before QKV (needs weights)
    cudaStreamWaitEvent(0, evJoin, 0);

    // QKV (q-scale folded into weights/bias)
    mma_gemm<0><<<dim3(9, 392), 256, GEMM_SMEM>>>(xw, wqkv, bqkv, nullptr, qkv, nullptr, 3 * DIM, DIM);

    // attention (tensor cores; 2 windows/block, overlapped table fetch, 4 CTAs/SM)
    attn_mma<<<dim3(512, HEADS), 256>>>(qkv, tbl, att);

    // proj + window reverse + unshift + residual
    mma_gemm<1><<<dim3(3, 392), 256, GEMM_SMEM>>>(att, wproj, proj_b, x, nullptr, y, DIM, DIM);

    // LN2
    ln_kernel<false><<<NTOK / 8, 256>>>(y, n2g, n2b, m);

    // FC1 + GELU
    mma_gemm<2><<<dim3(12, 392), 256, GEMM_SMEM>>>(m, wfc1, fc1_b, nullptr, h1, nullptr, 4 * DIM, DIM);

    // FC2 + residual -> output
    mma_gemm<3><<<dim3(3, 392), 256, GEMM_SMEM>>>(h1, wfc2, fc2_b, y, nullptr, out, DIM, 4 * DIM);
}

// round 15
// speedup vs baseline: 1.0128x; 1.0017x over previous
#include <cuda_runtime.h>
#include <cuda_bf16.h>
#include <cstdint>

#define DIM    384
#define NTOK   50176      // 1024 windows * 49 tokens
#define NWIN   1024
#define HEADS  12
#define HD     32
#define NWN    49
#define QSCALE 0.17677669529663689f  // 1/sqrt(32)

// ---------------- scratch (static device memory, no allocs) ----------------
__device__ __nv_bfloat16 g_xw [(size_t)NTOK * DIM];
__device__ __nv_bfloat16 g_qkv[(size_t)NTOK * 3 * DIM];
__device__ __nv_bfloat16 g_att[(size_t)NTOK * DIM];
__device__ float         g_y  [(size_t)NTOK * DIM];
__device__ __nv_bfloat16 g_m  [(size_t)NTOK * DIM];
__device__ __nv_bfloat16 g_h1 [(size_t)NTOK * 4 * DIM];
// weights stored TRANSPOSED: [N, K] K-major bf16
__device__ __nv_bfloat16 g_wqkv [3 * DIM * DIM];
__device__ __nv_bfloat16 g_wproj[DIM * DIM];
__device__ __nv_bfloat16 g_wfc1 [4 * DIM * DIM];
__device__ __nv_bfloat16 g_wfc2 [DIM * 4 * DIM];
__device__ float         g_bqkv [3 * DIM];              // q-prescaled qkv bias
__device__ __nv_bfloat16 g_tbl  [192 * 4096];           // bias+mask (bf16): [wcls][head][64][64]

// ---------------- helpers ----------------
__device__ __forceinline__ uint32_t smem_u32(const void* p) {
    uint32_t a;
    asm("{ .reg .u64 t; cvta.to.shared.u64 t, %1; cvt.u32.u64 %0, t; }" : "=r"(a) : "l"(p));
    return a;
}

#define CP_ASYNC16(dst, src) \
    asm volatile("cp.async.cg.shared.global [%0], [%1], 16;" :: "r"(dst), "l"(src) : "memory")
#define CP_ASYNC16_Z(dst, src, n) \
    asm volatile("cp.async.cg.shared.global [%0], [%1], 16, %2;" :: "r"(dst), "l"(src), "r"(n) : "memory")
#define CP_COMMIT() asm volatile("cp.async.commit_group;" ::: "memory")
#define CP_WAIT0()  asm volatile("cp.async.wait_group 0;" ::: "memory")
#define CP_WAIT1()  asm volatile("cp.async.wait_group 1;" ::: "memory")

__device__ __forceinline__ void ldmatrix_x4(uint32_t* r, uint32_t addr) {
    asm volatile("ldmatrix.sync.aligned.m8n8.x4.shared.b16 {%0,%1,%2,%3}, [%4];"
                 : "=r"(r[0]), "=r"(r[1]), "=r"(r[2]), "=r"(r[3]) : "r"(addr));
}
__device__ __forceinline__ void ldmatrix_x4_trans(uint32_t* r, uint32_t addr) {
    asm volatile("ldmatrix.sync.aligned.m8n8.x4.trans.shared.b16 {%0,%1,%2,%3}, [%4];"
                 : "=r"(r[0]), "=r"(r[1]), "=r"(r[2]), "=r"(r[3]) : "r"(addr));
}

__device__ __forceinline__ void mma_16816(float* c, const uint32_t* a, uint32_t b0, uint32_t b1) {
    asm volatile(
        "mma.sync.aligned.m16n8k16.row.col.f32.bf16.bf16.f32 "
        "{%0,%1,%2,%3}, {%4,%5,%6,%7}, {%8,%9}, {%0,%1,%2,%3};"
        : "+f"(c[0]), "+f"(c[1]), "+f"(c[2]), "+f"(c[3])
        : "r"(a[0]), "r"(a[1]), "r"(a[2]), "r"(a[3]), "r"(b0), "r"(b1));
}

__device__ __forceinline__ uint32_t pack_bf16(float lo, float hi) {
    __nv_bfloat162 p = __float22bfloat162_rn(make_float2(lo, hi));
    return *reinterpret_cast<uint32_t*>(&p);
}

// window-order row -> original token index
__device__ __forceinline__ int map_row(int r) {
    int win = r / NWN, n = r % NWN;
    int b = win >> 4, wIdx = win & 15;
    int hs = (wIdx >> 2) * 7 + n / 7;
    int ws = (wIdx & 3) * 7 + n % 7;
    int h = hs + 3; if (h >= 28) h -= 28;
    int w = ws + 3; if (w >= 28) w -= 28;
    return b * 784 + h * 28 + w;
}

// ---------------- merged setup: weight transpose-casts + bias prescale + bias/mask table ----
__global__ __launch_bounds__(256)
void cvt_all(const float* __restrict__ qkv_w, const float* __restrict__ proj_w,
             const float* __restrict__ fc1_w, const float* __restrict__ fc2_w,
             const float* __restrict__ qkv_b, const float* __restrict__ rpb) {
    const int t = blockIdx.x;
    const int tid = threadIdx.x;

    if (t >= 1728) {                         // table part
        const int b = t - 1728;              // 0..191 = wcls*12 + head
        const int wIdx = b / 12, head = b % 12;
        for (int i = tid; i < 4096; i += 256) {
            int r = i >> 6, c = i & 63;
            float v = -1e30f;
            if (r < NWN && c < NWN) {
                int rh = r / 7, rw = r % 7, chh = c / 7, cww = c % 7;
                int di = rh - chh + 6, dj = rw - cww + 6;
                v = rpb[(di * 13 + dj) * HEADS + head];
                int hh_r = (wIdx >> 2) * 7 + rh, ww_r = (wIdx & 3) * 7 + rw;
                int hh_c = (wIdx >> 2) * 7 + chh, ww_c = (wIdx & 3) * 7 + cww;
                int clr = (hh_r < 21 ? 0 : (hh_r < 25 ? 1 : 2)) * 3 + (ww_r < 21 ? 0 : (ww_r < 25 ? 1 : 2));
                int clc = (hh_c < 21 ? 0 : (hh_c < 25 ? 1 : 2)) * 3 + (ww_c < 21 ? 0 : (ww_c < 25 ? 1 : 2));
                if (clr != clc) v -= 100.f;
            }
            g_tbl[((size_t)b << 12) + i] = __float2bfloat16(v);
        }
        return;
    }

    __shared__ float tile[32][33];
    const int tx = tid & 31, ty = tid >> 5;

    if (t < 5) {
        int idx = t * 256 + tid;
        if (idx < 3 * DIM)
            g_bqkv[idx] = qkv_b[idx] * (idx < DIM ? QSCALE : 1.f);
    }

    const float* src; __nv_bfloat16* dst;
    int K, N, tn, tk;
    float scale0 = 1.f;
    if (t < 432)       { src = qkv_w;  dst = g_wqkv;  K = 384;  N = 1152; tn = t % 36;          tk = t / 36;          scale0 = QSCALE; }
    else if (t < 576)  { src = proj_w; dst = g_wproj; K = 384;  N = 384;  tn = (t - 432) % 12;  tk = (t - 432) / 12; }
    else if (t < 1152) { src = fc1_w;  dst = g_wfc1;  K = 384;  N = 1536; tn = (t - 576) % 48;  tk = (t - 576) / 48; }
    else               { src = fc2_w;  dst = g_wfc2;  K = 1536; N = 384;  tn = (t - 1152) % 12; tk = (t - 1152) / 12; }

    int k0 = tk * 32, n0 = tn * 32;
#pragma unroll
    for (int i = 0; i < 4; i++)
        tile[ty + i * 8][tx] = src[(size_t)(k0 + ty + i * 8) * N + n0 + tx];
    __syncthreads();
#pragma unroll
    for (int i = 0; i < 4; i++) {
        int n = n0 + ty + i * 8;
        float s = (n < 384) ? scale0 : 1.f;
        dst[(size_t)n * K + k0 + tx] = __float2bfloat16(tile[tx][ty + i * 8] * s);
    }
}

// ---------------- LayerNorm: one warp per row, no smem, no syncthreads ----------------
template<bool PERM>
__global__ __launch_bounds__(256)
void ln_kernel(const float* __restrict__ in,
               const float* __restrict__ gamma,
               const float* __restrict__ beta,
               __nv_bfloat16* __restrict__ out) {
    const int wid = threadIdx.x >> 5, lane = threadIdx.x & 31;
    const int r = blockIdx.x * 8 + wid;
    const int src = PERM ? map_row(r) : r;
    const float* row = in + (size_t)src * DIM;

    float4 v[3];
    float s = 0.f, s2 = 0.f;
#pragma unroll
    for (int i = 0; i < 3; i++) {
        v[i] = *reinterpret_cast<const float4*>(&row[lane * 4 + i * 128]);
        s  += v[i].x + v[i].y + v[i].z + v[i].w;
        s2 += v[i].x * v[i].x + v[i].y * v[i].y + v[i].z * v[i].z + v[i].w * v[i].w;
    }
#pragma unroll
    for (int o = 16; o; o >>= 1) {
        s  += __shfl_xor_sync(0xffffffffu, s,  o);
        s2 += __shfl_xor_sync(0xffffffffu, s2, o);
    }
    float mean = s * (1.f / DIM);
    float rstd = rsqrtf(s2 * (1.f / DIM) - mean * mean + 1e-5f);

#pragma unroll
    for (int i = 0; i < 3; i++) {
        int c = lane * 4 + i * 128;
        float4 g = *reinterpret_cast<const float4*>(&gamma[c]);
        float4 b = *reinterpret_cast<const float4*>(&beta[c]);
        float o0 = (v[i].x - mean) * rstd * g.x + b.x;
        float o1 = (v[i].y - mean) * rstd * g.y + b.y;
        float o2 = (v[i].z - mean) * rstd * g.z + b.z;
        float o3 = (v[i].w - mean) * rstd * g.w + b.w;
        uint2 pk = make_uint2(pack_bf16(o0, o1), pack_bf16(o2, o3));
        *reinterpret_cast<uint2*>(&out[(size_t)r * DIM + c]) = pk;
    }
}

// ---------------- mma.sync GEMM: 128x128x32 CTA tile, 8 warps of 32x64, 4 stages ----------------
#define STAGE_B 16384
#define NSTAGE  4
#define GEMM_SMEM (NSTAGE * STAGE_B)

template<int MODE>
__global__ __launch_bounds__(256, 2)
void mma_gemm(const __nv_bfloat16* __restrict__ A,
              const __nv_bfloat16* __restrict__ B,
              const float* __restrict__ bias,
              const float* __restrict__ resid,
              __nv_bfloat16* __restrict__ outb,
              float* __restrict__ outf,
              int N, int K) {
    extern __shared__ __align__(1024) char smem[];   // per stage: A 8KB | B 8KB
    const uint32_t sbase = smem_u32(smem);

    const int tid = threadIdx.x;
    const int wid = tid >> 5, lane = tid & 31;
    const int warpM = wid >> 1;
    const int warpN = wid & 1;
    const int m0 = blockIdx.y * 128, n0 = blockIdx.x * 128;

    float acc[2][8][4];
#pragma unroll
    for (int i = 0; i < 2; i++)
#pragma unroll
        for (int j = 0; j < 8; j++)
#pragma unroll
            for (int q = 0; q < 4; q++) acc[i][j][q] = 0.f;

    const int nch = K >> 5;
    const int lr = tid >> 2;
    const int lc = tid & 3;
    auto load_stage = [&](int s, int c) {
        uint32_t st = sbase + s * STAGE_B;
        int k0 = c * 32;
#pragma unroll
        for (int i = 0; i < 2; i++) {
            int r = lr + i * 64;
            uint32_t sw = (uint32_t)((lc ^ ((r >> 1) & 3)) << 4);
            CP_ASYNC16(st + r * 64 + sw, A + (size_t)(m0 + r) * K + k0 + lc * 8);
        }
#pragma unroll
        for (int i = 0; i < 2; i++) {
            int r = lr + i * 64;
            uint32_t sw = (uint32_t)((lc ^ ((r >> 1) & 3)) << 4);
            CP_ASYNC16(st + 8192 + r * 64 + sw, B + (size_t)(n0 + r) * K + k0 + lc * 8);
        }
        CP_COMMIT();
    };

    load_stage(0, 0);
    if (nch > 1) load_stage(1, 1);
    if (nch > 2) load_stage(2, 2);

    const int lrow = lane & 15;
    const int lhalf = lane >> 4;

    for (int c = 0; c < nch; c++) {
        if (c + 2 < nch)      asm volatile("cp.async.wait_group 2;" ::: "memory");
        else if (c + 1 < nch) asm volatile("cp.async.wait_group 1;" ::: "memory");
        else                  asm volatile("cp.async.wait_group 0;" ::: "memory");
        __syncthreads();
        if (c + 3 < nch) load_stage((c + 3) & 3, c + 3);

        uint32_t sA = sbase + (c & 3) * STAGE_B;
        uint32_t sB = sA + 8192;

        uint32_t a[2][2][4];
#pragma unroll
        for (int kh = 0; kh < 2; kh++)
#pragma unroll
            for (int mt = 0; mt < 2; mt++) {
                int r = warpM * 32 + mt * 16 + lrow;
                int chunk = kh * 2 + lhalf;
                ldmatrix_x4(a[kh][mt], sA + r * 64 + (uint32_t)((chunk ^ ((r >> 1) & 3)) << 4));
            }
#pragma unroll
        for (int kh = 0; kh < 2; kh++) {
            int chunk = kh * 2 + lhalf;
#pragma unroll
            for (int np = 0; np < 4; np++) {
                uint32_t b[4];
                int r = warpN * 64 + np * 16 + lrow;
                ldmatrix_x4(b, sB + r * 64 + (uint32_t)((chunk ^ ((r >> 1) & 3)) << 4));
#pragma unroll
                for (int mt = 0; mt < 2; mt++) {
                    mma_16816(acc[mt][2 * np],     a[kh][mt], b[0], b[2]);
                    mma_16816(acc[mt][2 * np + 1], a[kh][mt], b[1], b[3]);
                }
            }
        }
    }

    // ---------------- fused epilogue on register accumulators ----------------
    const int colq = (lane & 3) * 2;
#pragma unroll
    for (int mt = 0; mt < 2; mt++) {
        int grow0 = m0 + warpM * 32 + mt * 16 + (lane >> 2);
        int grow1 = grow0 + 8;
        int dst0 = (MODE == 1) ? map_row(grow0) : grow0;
        int dst1 = (MODE == 1) ? map_row(grow1) : grow1;
#pragma unroll
        for (int nt = 0; nt < 8; nt++) {
            int gc = n0 + warpN * 64 + nt * 8 + colq;
            float b0 = bias[gc], b1 = bias[gc + 1];
            float v00 = acc[mt][nt][0] + b0, v01 = acc[mt][nt][1] + b1;
            float v10 = acc[mt][nt][2] + b0, v11 = acc[mt][nt][3] + b1;
            if (MODE == 0) {
                *reinterpret_cast<__nv_bfloat162*>(&outb[(size_t)grow0 * N + gc]) =
                    __nv_bfloat162(__float2bfloat16(v00), __float2bfloat16(v01));
                *reinterpret_cast<__nv_bfloat162*>(&outb[(size_t)grow1 * N + gc]) =
                    __nv_bfloat162(__float2bfloat16(v10), __float2bfloat16(v11));
            } else if (MODE == 1) {
                const float2 r0 = *reinterpret_cast<const float2*>(&resid[(size_t)dst0 * N + gc]);
                const float2 r1 = *reinterpret_cast<const float2*>(&resid[(size_t)dst1 * N + gc]);
                *reinterpret_cast<float2*>(&outf[(size_t)dst0 * N + gc]) =
                    make_float2(v00 + r0.x, v01 + r0.y);
                *reinterpret_cast<float2*>(&outf[(size_t)dst1 * N + gc]) =
                    make_float2(v10 + r1.x, v11 + r1.y);
            } else if (MODE == 2) {
                v00 = 0.5f * v00 * (1.0f + erff(v00 * 0.7071067811865475f));
                v01 = 0.5f * v01 * (1.0f + erff(v01 * 0.7071067811865475f));
                v10 = 0.5f * v10 * (1.0f + erff(v10 * 0.7071067811865475f));
                v11 = 0.5f * v11 * (1.0f + erff(v11 * 0.7071067811865475f));
                *reinterpret_cast<__nv_bfloat162*>(&outb[(size_t)grow0 * N + gc]) =
                    __nv_bfloat162(__float2bfloat16(v00), __float2bfloat16(v01));
                *reinterpret_cast<__nv_bfloat162*>(&outb[(size_t)grow1 * N + gc]) =
                    __nv_bfloat162(__float2bfloat16(v10), __float2bfloat16(v11));
            } else {
                const float2 r0 = *reinterpret_cast<const float2*>(&resid[(size_t)grow0 * N + gc]);
                const float2 r1 = *reinterpret_cast<const float2*>(&resid[(size_t)grow1 * N + gc]);
                *reinterpret_cast<float2*>(&outf[(size_t)grow0 * N + gc]) =
                    make_float2(v00 + r0.x, v01 + r0.y);
                *reinterpret_cast<float2*>(&outf[(size_t)grow1 * N + gc]) =
                    make_float2(v10 + r1.x, v11 + r1.y);
            }
        }
    }
}

// ---------------- tensor-core windowed attention: block = (2 windows, head) ----------------
// pairs windows (win_base + bx, win_base + bx + 256): share (win & 15) table slice
#define TBL_STRIDE 144
__global__ __launch_bounds__(256, 4)
void attn_mma(const __nv_bfloat16* __restrict__ qkv,
              const __nv_bfloat16* __restrict__ tbl,
              __nv_bfloat16* __restrict__ out,
              int win_base) {
    __shared__ __align__(1024) char sq[2][4096];
    __shared__ __align__(1024) char sk[2][4096];
    __shared__ __align__(1024) char sv[2][4096];
    __shared__ __align__(16)   char stbl[64 * TBL_STRIDE];

    const int tid = threadIdx.x;
    const int sub = tid >> 7;
    const int t2 = tid & 127;
    const int lane = tid & 31, w4 = (tid >> 5) & 3;
    const int win = win_base + blockIdx.x + sub * 256;
    const int head = blockIdx.y;
    const uint32_t qb = smem_u32(sq[sub]), kb = smem_u32(sk[sub]), vb = smem_u32(sv[sub]);
    const uint32_t tbase = smem_u32(stbl);

    // group 0: q/k/v staging
    const char* basep = reinterpret_cast<const char*>(qkv + (size_t)win * NWN * 1152 + head * HD);
#pragma unroll
    for (int i = t2; i < 256; i += 128) {
        int r = i >> 2, c = i & 3;
        int n = (r < NWN) ? 16 : 0;
        const char* p = basep + (size_t)r * 2304;
        uint32_t sw = (uint32_t)((c ^ ((r >> 1) & 3)) << 4);
        CP_ASYNC16_Z(qb + r * 64 + sw, p + c * 16, n);
        CP_ASYNC16_Z(kb + r * 64 + sw, p + 768 + c * 16, n);
        CP_ASYNC16_Z(vb + r * 64 + sw, p + 1536 + c * 16, n);
    }
    CP_COMMIT();

    // group 1: table slice (needed only after S MMAs)
    {
        const char* g = reinterpret_cast<const char*>(
            tbl + (((size_t)((blockIdx.x & 15) * 12 + head)) << 12));
#pragma unroll
        for (int i = tid; i < 512; i += 256) {
            int r = i >> 3, c16 = i & 7;
            CP_ASYNC16(tbase + r * TBL_STRIDE + c16 * 16, g + i * 16);
        }
    }
    CP_COMMIT();

    CP_WAIT1();
    __syncthreads();

    const int lrow = lane & 15, lhalf = lane >> 4;

    // ---- S = q k^T ----
    float sacc[8][4];
#pragma unroll
    for (int t = 0; t < 8; t++)
#pragma unroll
        for (int q = 0; q < 4; q++) sacc[t][q] = 0.f;

    uint32_t af[2][4];
#pragma unroll
    for (int kh = 0; kh < 2; kh++) {
        int r = w4 * 16 + lrow;
        int chunk = kh * 2 + lhalf;
        ldmatrix_x4(af[kh], qb + r * 64 + (uint32_t)((chunk ^ ((r >> 1) & 3)) << 4));
    }
#pragma unroll
    for (int kh = 0; kh < 2; kh++) {
        int chunk = kh * 2 + lhalf;
        uint32_t b[4][4];
#pragma unroll
        for (int np = 0; np < 4; np++) {
            int r = np * 16 + lrow;
            ldmatrix_x4(b[np], kb + r * 64 + (uint32_t)((chunk ^ ((r >> 1) & 3)) << 4));
        }
#pragma unroll
        for (int np = 0; np < 4; np++) {
            mma_16816(sacc[2 * np],     af[kh], b[np][0], b[np][2]);
            mma_16816(sacc[2 * np + 1], af[kh], b[np][1], b[np][3]);
        }
    }

    CP_WAIT0();
    __syncthreads();

    // ---- bias + mask from smem table ----
    const int r0 = w4 * 16 + (lane >> 2), r1 = r0 + 8;
    const int c0 = 2 * (lane & 3);
    const uint32_t tb0 = tbase + r0 * TBL_STRIDE + c0 * 2;
#pragma unroll
    for (int t = 0; t < 8; t++) {
        uint32_t u0, u1;
        asm volatile("ld.shared.b32 %0, [%1];" : "=r"(u0) : "r"(tb0 + 16 * t));
        asm volatile("ld.shared.b32 %0, [%1];" : "=r"(u1) : "r"(tb0 + 8 * TBL_STRIDE + 16 * t));
        float2 b0 = __bfloat1622float2(*reinterpret_cast<__nv_bfloat162*>(&u0));
        float2 b1 = __bfloat1622float2(*reinterpret_cast<__nv_bfloat162*>(&u1));
        sacc[t][0] += b0.x; sacc[t][1] += b0.y;
        sacc[t][2] += b1.x; sacc[t][3] += b1.y;
    }

    // ---- softmax ----
    float mx0 = -1e30f, mx1 = -1e30f;
#pragma unroll
    for (int t = 0; t < 8; t++) {
        mx0 = fmaxf(mx0, fmaxf(sacc[t][0], sacc[t][1]));
        mx1 = fmaxf(mx1, fmaxf(sacc[t][2], sacc[t][3]));
    }
    mx0 = fmaxf(mx0, __shfl_xor_sync(0xffffffffu, mx0, 1));
    mx0 = fmaxf(mx0, __shfl_xor_sync(0xffffffffu, mx0, 2));
    mx1 = fmaxf(mx1, __shfl_xor_sync(0xffffffffu, mx1, 1));
    mx1 = fmaxf(mx1, __shfl_xor_sync(0xffffffffu, mx1, 2));
    float s0 = 0.f, s1 = 0.f;
#pragma unroll
    for (int t = 0; t < 8; t++) {
        float e0 = __expf(sacc[t][0] - mx0); sacc[t][0] = e0; s0 += e0;
        float e1 = __expf(sacc[t][1] - mx0); sacc[t][1] = e1; s0 += e1;
        float e2 = __expf(sacc[t][2] - mx1); sacc[t][2] = e2; s1 += e2;
        float e3 = __expf(sacc[t][3] - mx1); sacc[t][3] = e3; s1 += e3;
    }
    s0 += __shfl_xor_sync(0xffffffffu, s0, 1);
    s0 += __shfl_xor_sync(0xffffffffu, s0, 2);
    s1 += __shfl_xor_sync(0xffffffffu, s1, 1);
    s1 += __shfl_xor_sync(0xffffffffu, s1, 2);
    float inv0 = 1.f / s0, inv1 = 1.f / s1;
#pragma unroll
    for (int t = 0; t < 8; t++) {
        sacc[t][0] *= inv0; sacc[t][1] *= inv0;
        sacc[t][2] *= inv1; sacc[t][3] *= inv1;
    }

    // ---- out = P V ----
    float oacc[4][4];
#pragma unroll
    for (int t = 0; t < 4; t++)
#pragma unroll
        for (int q = 0; q < 4; q++) oacc[t][q] = 0.f;

#pragma unroll
    for (int j = 0; j < 4; j++) {
        uint32_t pa[4];
        pa[0] = pack_bf16(sacc[2 * j][0],     sacc[2 * j][1]);
        pa[1] = pack_bf16(sacc[2 * j][2],     sacc[2 * j][3]);
        pa[2] = pack_bf16(sacc[2 * j + 1][0], sacc[2 * j + 1][1]);
        pa[3] = pack_bf16(sacc[2 * j + 1][2], sacc[2 * j + 1][3]);
        int vr = j * 16 + ((lane >> 3) & 1) * 8 + (lane & 7);
        uint32_t t4[2][4];
#pragma unroll
        for (int dblk = 0; dblk < 2; dblk++) {
            int chunk = dblk * 2 + (lane >> 4);
            ldmatrix_x4_trans(t4[dblk], vb + vr * 64 + (uint32_t)((chunk ^ ((vr >> 1) & 3)) << 4));
        }
#pragma unroll
        for (int dblk = 0; dblk < 2; dblk++) {
            mma_16816(oacc[2 * dblk],     pa, t4[dblk][0], t4[dblk][1]);
            mma_16816(oacc[2 * dblk + 1], pa, t4[dblk][2], t4[dblk][3]);
        }
    }

    if (r0 < NWN) {
        size_t ob = ((size_t)win * NWN + r0) * DIM + head * HD;
#pragma unroll
        for (int t = 0; t < 4; t++) {
            int d = 8 * t + c0;
            *reinterpret_cast<__nv_bfloat162*>(&out[ob + d]) =
                __nv_bfloat162(__float2bfloat16(oacc[t][0]), __float2bfloat16(oacc[t][1]));
        }
    }
    if (r1 < NWN) {
        size_t ob = ((size_t)win * NWN + r1) * DIM + head * HD;
#pragma unroll
        for (int t = 0; t < 4; t++) {
            int d = 8 * t + c0;
            *reinterpret_cast<__nv_bfloat162*>(&out[ob + d]) =
                __nv_bfloat162(__float2bfloat16(oacc[t][2]), __float2bfloat16(oacc[t][3]));
        }
    }
}

// ---------------- launch ----------------
#define HTOK (NTOK / 2)   // 25088 rows = windows 0..511

extern "C" void kernel_launch(void* const* d_in, const int* in_sizes, int n_in,
                              void* d_out, int out_size) {
    const float* x      = (const float*)d_in[0];
    const float* n1g    = (const float*)d_in[1];
    const float* n1b    = (const float*)d_in[2];
    const float* qkv_w  = (const float*)d_in[3];
    const float* qkv_b  = (const float*)d_in[4];
    const float* proj_w = (const float*)d_in[5];
    const float* proj_b = (const float*)d_in[6];
    const float* rpb    = (const float*)d_in[7];
    const float* n2g    = (const float*)d_in[8];
    const float* n2b    = (const float*)d_in[9];
    const float* fc1_w  = (const float*)d_in[10];
    const float* fc1_b  = (const float*)d_in[11];
    const float* fc2_w  = (const float*)d_in[12];
    const float* fc2_b  = (const float*)d_in[13];
    float* out = (float*)d_out;

    __nv_bfloat16 *xw, *qkv, *att, *m, *h1, *wqkv, *wproj, *wfc1, *wfc2, *tbl;
    float *y, *bqkv;
    cudaGetSymbolAddress((void**)&xw,    g_xw);
    cudaGetSymbolAddress((void**)&qkv,   g_qkv);
    cudaGetSymbolAddress((void**)&att,   g_att);
    cudaGetSymbolAddress((void**)&y,     g_y);
    cudaGetSymbolAddress((void**)&m,     g_m);
    cudaGetSymbolAddress((void**)&h1,    g_h1);
    cudaGetSymbolAddress((void**)&wqkv,  g_wqkv);
    cudaGetSymbolAddress((void**)&wproj, g_wproj);
    cudaGetSymbolAddress((void**)&wfc1,  g_wfc1);
    cudaGetSymbolAddress((void**)&wfc2,  g_wfc2);
    cudaGetSymbolAddress((void**)&bqkv,  g_bqkv);
    cudaGetSymbolAddress((void**)&tbl,   g_tbl);

    cudaFuncSetAttribute(mma_gemm<0>, cudaFuncAttributeMaxDynamicSharedMemorySize, GEMM_SMEM);
    cudaFuncSetAttribute(mma_gemm<1>, cudaFuncAttributeMaxDynamicSharedMemorySize, GEMM_SMEM);
    cudaFuncSetAttribute(mma_gemm<2>, cudaFuncAttributeMaxDynamicSharedMemorySize, GEMM_SMEM);
    cudaFuncSetAttribute(mma_gemm<3>, cudaFuncAttributeMaxDynamicSharedMemorySize, GEMM_SMEM);

    static cudaStream_t s1 = nullptr;
    static cudaEvent_t evFork = nullptr, evJoin = nullptr, evA = nullptr, evB = nullptr;
    if (!s1) {
        cudaStreamCreateWithFlags(&s1, cudaStreamNonBlocking);
        cudaEventCreateWithFlags(&evFork, cudaEventDisableTiming);
        cudaEventCreateWithFlags(&evJoin, cudaEventDisableTiming);
        cudaEventCreateWithFlags(&evA, cudaEventDisableTiming);
        cudaEventCreateWithFlags(&evB, cudaEventDisableTiming);
    }

    // fork: cvt_all concurrent with LN1
    cudaEventRecord(evFork, 0);
    cudaStreamWaitEvent(s1, evFork, 0);
    cvt_all<<<1920, 256, 0, s1>>>(qkv_w, proj_w, fc1_w, fc2_w, qkv_b, rpb);
    cudaEventRecord(evJoin, s1);

    ln_kernel<true><<<NTOK / 8, 256>>>(x, n1g, n1b, xw);
    cudaStreamWaitEvent(0, evJoin, 0);

    // QKV first half (rows 0..25087 = windows 0..511)
    mma_gemm<0><<<dim3(9, 196), 256, GEMM_SMEM>>>(xw, wqkv, bqkv, nullptr, qkv, nullptr, 3 * DIM, DIM);
    cudaEventRecord(evA, 0);

    // attn first half on side stream, overlapped with QKV second half
    cudaStreamWaitEvent(s1, evA, 0);
    attn_mma<<<dim3(256, HEADS), 256, 0, s1>>>(qkv, tbl, att, 0);
    cudaEventRecord(evB, s1);

    // QKV second half (rows 25088..) on main
    mma_gemm<0><<<dim3(9, 196), 256, GEMM_SMEM>>>(xw + (size_t)HTOK * DIM, wqkv, bqkv, nullptr,
                                                  qkv + (size_t)HTOK * 3 * DIM, nullptr, 3 * DIM, DIM);
    // attn second half on main
    attn_mma<<<dim3(256, HEADS), 256>>>(qkv, tbl, att, 512);

    // join: proj needs both attention halves
    cudaStreamWaitEvent(0, evB, 0);

    mma_gemm<1><<<dim3(3, 392), 256, GEMM_SMEM>>>(att, wproj, proj_b, x, nullptr, y, DIM, DIM);
    ln_kernel<false><<<NTOK / 8, 256>>>(y, n2g, n2b, m);
    mma_gemm<2><<<dim3(12, 392), 256, GEMM_SMEM>>>(m, wfc1, fc1_b, nullptr, h1, nullptr, 4 * DIM, DIM);
    mma_gemm<3><<<dim3(3, 392), 256, GEMM_SMEM>>>(h1, wfc2, fc2_b, y, nullptr, out, DIM, 4 * DIM);
}

// round 16
// speedup vs baseline: 1.0322x; 1.0191x over previous
#include <cuda_runtime.h>
#include <cuda_bf16.h>
#include <cstdint>

#define DIM    384
#define NTOK   50176      // 1024 windows * 49 tokens
#define NWIN   1024
#define HEADS  12
#define HD     32
#define NWN    49
#define QSCALE 0.17677669529663689f  // 1/sqrt(32)
#define HTOK   (NTOK / 2)            // 25088 rows = windows 0..511 (batches 0..31)

// ---------------- scratch (static device memory, no allocs) ----------------
__device__ __nv_bfloat16 g_xw [(size_t)NTOK * DIM];
__device__ __nv_bfloat16 g_qkv[(size_t)NTOK * 3 * DIM];
__device__ __nv_bfloat16 g_att[(size_t)NTOK * DIM];
__device__ float         g_y  [(size_t)NTOK * DIM];
__device__ __nv_bfloat16 g_m  [(size_t)NTOK * DIM];
__device__ __nv_bfloat16 g_h1 [(size_t)NTOK * 4 * DIM];
// weights stored TRANSPOSED: [N, K] K-major bf16
__device__ __nv_bfloat16 g_wqkv [3 * DIM * DIM];
__device__ __nv_bfloat16 g_wproj[DIM * DIM];
__device__ __nv_bfloat16 g_wfc1 [4 * DIM * DIM];
__device__ __nv_bfloat16 g_wfc2 [DIM * 4 * DIM];
__device__ float         g_bqkv [3 * DIM];              // q-prescaled qkv bias
__device__ __nv_bfloat16 g_tbl  [192 * 4096];           // bias+mask (bf16): [wcls][head][64][64]

// ---------------- helpers ----------------
__device__ __forceinline__ uint32_t smem_u32(const void* p) {
    uint32_t a;
    asm("{ .reg .u64 t; cvta.to.shared.u64 t, %1; cvt.u32.u64 %0, t; }" : "=r"(a) : "l"(p));
    return a;
}

#define CP_ASYNC16(dst, src) \
    asm volatile("cp.async.cg.shared.global [%0], [%1], 16;" :: "r"(dst), "l"(src) : "memory")
#define CP_ASYNC16_Z(dst, src, n) \
    asm volatile("cp.async.cg.shared.global [%0], [%1], 16, %2;" :: "r"(dst), "l"(src), "r"(n) : "memory")
#define CP_COMMIT() asm volatile("cp.async.commit_group;" ::: "memory")
#define CP_WAIT0()  asm volatile("cp.async.wait_group 0;" ::: "memory")
#define CP_WAIT1()  asm volatile("cp.async.wait_group 1;" ::: "memory")

__device__ __forceinline__ void ldmatrix_x4(uint32_t* r, uint32_t addr) {
    asm volatile("ldmatrix.sync.aligned.m8n8.x4.shared.b16 {%0,%1,%2,%3}, [%4];"
                 : "=r"(r[0]), "=r"(r[1]), "=r"(r[2]), "=r"(r[3]) : "r"(addr));
}
__device__ __forceinline__ void ldmatrix_x4_trans(uint32_t* r, uint32_t addr) {
    asm volatile("ldmatrix.sync.aligned.m8n8.x4.trans.shared.b16 {%0,%1,%2,%3}, [%4];"
                 : "=r"(r[0]), "=r"(r[1]), "=r"(r[2]), "=r"(r[3]) : "r"(addr));
}

__device__ __forceinline__ void mma_16816(float* c, const uint32_t* a, uint32_t b0, uint32_t b1) {
    asm volatile(
        "mma.sync.aligned.m16n8k16.row.col.f32.bf16.bf16.f32 "
        "{%0,%1,%2,%3}, {%4,%5,%6,%7}, {%8,%9}, {%0,%1,%2,%3};"
        : "+f"(c[0]), "+f"(c[1]), "+f"(c[2]), "+f"(c[3])
        : "r"(a[0]), "r"(a[1]), "r"(a[2]), "r"(a[3]), "r"(b0), "r"(b1));
}

__device__ __forceinline__ uint32_t pack_bf16(float lo, float hi) {
    __nv_bfloat162 p = __float22bfloat162_rn(make_float2(lo, hi));
    return *reinterpret_cast<uint32_t*>(&p);
}

// window-order row -> original token index (closed within each half of rows)
__device__ __forceinline__ int map_row(int r) {
    int win = r / NWN, n = r % NWN;
    int b = win >> 4, wIdx = win & 15;
    int hs = (wIdx >> 2) * 7 + n / 7;
    int ws = (wIdx & 3) * 7 + n % 7;
    int h = hs + 3; if (h >= 28) h -= 28;
    int w = ws + 3; if (w >= 28) w -= 28;
    return b * 784 + h * 28 + w;
}

// ---------------- merged setup: weight transpose-casts + bias prescale + bias/mask table ----
__global__ __launch_bounds__(256)
void cvt_all(const float* __restrict__ qkv_w, const float* __restrict__ proj_w,
             const float* __restrict__ fc1_w, const float* __restrict__ fc2_w,
             const float* __restrict__ qkv_b, const float* __restrict__ rpb) {
    const int t = blockIdx.x;
    const int tid = threadIdx.x;

    if (t >= 1728) {                         // table part
        const int b = t - 1728;              // 0..191 = wcls*12 + head
        const int wIdx = b / 12, head = b % 12;
        for (int i = tid; i < 4096; i += 256) {
            int r = i >> 6, c = i & 63;
            float v = -1e30f;
            if (r < NWN && c < NWN) {
                int rh = r / 7, rw = r % 7, chh = c / 7, cww = c % 7;
                int di = rh - chh + 6, dj = rw - cww + 6;
                v = rpb[(di * 13 + dj) * HEADS + head];
                int hh_r = (wIdx >> 2) * 7 + rh, ww_r = (wIdx & 3) * 7 + rw;
                int hh_c = (wIdx >> 2) * 7 + chh, ww_c = (wIdx & 3) * 7 + cww;
                int clr = (hh_r < 21 ? 0 : (hh_r < 25 ? 1 : 2)) * 3 + (ww_r < 21 ? 0 : (ww_r < 25 ? 1 : 2));
                int clc = (hh_c < 21 ? 0 : (hh_c < 25 ? 1 : 2)) * 3 + (ww_c < 21 ? 0 : (ww_c < 25 ? 1 : 2));
                if (clr != clc) v -= 100.f;
            }
            g_tbl[((size_t)b << 12) + i] = __float2bfloat16(v);
        }
        return;
    }

    __shared__ float tile[32][33];
    const int tx = tid & 31, ty = tid >> 5;

    if (t < 5) {
        int idx = t * 256 + tid;
        if (idx < 3 * DIM)
            g_bqkv[idx] = qkv_b[idx] * (idx < DIM ? QSCALE : 1.f);
    }

    const float* src; __nv_bfloat16* dst;
    int K, N, tn, tk;
    float scale0 = 1.f;
    if (t < 432)       { src = qkv_w;  dst = g_wqkv;  K = 384;  N = 1152; tn = t % 36;          tk = t / 36;          scale0 = QSCALE; }
    else if (t < 576)  { src = proj_w; dst = g_wproj; K = 384;  N = 384;  tn = (t - 432) % 12;  tk = (t - 432) / 12; }
    else if (t < 1152) { src = fc1_w;  dst = g_wfc1;  K = 384;  N = 1536; tn = (t - 576) % 48;  tk = (t - 576) / 48; }
    else               { src = fc2_w;  dst = g_wfc2;  K = 1536; N = 384;  tn = (t - 1152) % 12; tk = (t - 1152) / 12; }

    int k0 = tk * 32, n0 = tn * 32;
#pragma unroll
    for (int i = 0; i < 4; i++)
        tile[ty + i * 8][tx] = src[(size_t)(k0 + ty + i * 8) * N + n0 + tx];
    __syncthreads();
#pragma unroll
    for (int i = 0; i < 4; i++) {
        int n = n0 + ty + i * 8;
        float s = (n < 384) ? scale0 : 1.f;
        dst[(size_t)n * K + k0 + tx] = __float2bfloat16(tile[tx][ty + i * 8] * s);
    }
}

// ---------------- LayerNorm: one warp per row ----------------
template<bool PERM>
__global__ __launch_bounds__(256)
void ln_kernel(const float* __restrict__ in,
               const float* __restrict__ gamma,
               const float* __restrict__ beta,
               __nv_bfloat16* __restrict__ out) {
    const int wid = threadIdx.x >> 5, lane = threadIdx.x & 31;
    const int r = blockIdx.x * 8 + wid;
    const int src = PERM ? map_row(r) : r;
    const float* row = in + (size_t)src * DIM;

    float4 v[3];
    float s = 0.f, s2 = 0.f;
#pragma unroll
    for (int i = 0; i < 3; i++) {
        v[i] = *reinterpret_cast<const float4*>(&row[lane * 4 + i * 128]);
        s  += v[i].x + v[i].y + v[i].z + v[i].w;
        s2 += v[i].x * v[i].x + v[i].y * v[i].y + v[i].z * v[i].z + v[i].w * v[i].w;
    }
#pragma unroll
    for (int o = 16; o; o >>= 1) {
        s  += __shfl_xor_sync(0xffffffffu, s,  o);
        s2 += __shfl_xor_sync(0xffffffffu, s2, o);
    }
    float mean = s * (1.f / DIM);
    float rstd = rsqrtf(s2 * (1.f / DIM) - mean * mean + 1e-5f);

#pragma unroll
    for (int i = 0; i < 3; i++) {
        int c = lane * 4 + i * 128;
        float4 g = *reinterpret_cast<const float4*>(&gamma[c]);
        float4 b = *reinterpret_cast<const float4*>(&beta[c]);
        float o0 = (v[i].x - mean) * rstd * g.x + b.x;
        float o1 = (v[i].y - mean) * rstd * g.y + b.y;
        float o2 = (v[i].z - mean) * rstd * g.z + b.z;
        float o3 = (v[i].w - mean) * rstd * g.w + b.w;
        uint2 pk = make_uint2(pack_bf16(o0, o1), pack_bf16(o2, o3));
        *reinterpret_cast<uint2*>(&out[(size_t)r * DIM + c]) = pk;
    }
}

// ---------------- mma.sync GEMM: 128x128x32 CTA tile, yoff = row-tile offset ----------------
#define STAGE_B 16384
#define NSTAGE  4
#define GEMM_SMEM (NSTAGE * STAGE_B)

template<int MODE>
__global__ __launch_bounds__(256, 2)
void mma_gemm(const __nv_bfloat16* __restrict__ A,
              const __nv_bfloat16* __restrict__ B,
              const float* __restrict__ bias,
              const float* __restrict__ resid,
              __nv_bfloat16* __restrict__ outb,
              float* __restrict__ outf,
              int N, int K, int yoff) {
    extern __shared__ __align__(1024) char smem[];
    const uint32_t sbase = smem_u32(smem);

    const int tid = threadIdx.x;
    const int wid = tid >> 5, lane = tid & 31;
    const int warpM = wid >> 1;
    const int warpN = wid & 1;
    const int m0 = (blockIdx.y + yoff) * 128, n0 = blockIdx.x * 128;

    float acc[2][8][4];
#pragma unroll
    for (int i = 0; i < 2; i++)
#pragma unroll
        for (int j = 0; j < 8; j++)
#pragma unroll
            for (int q = 0; q < 4; q++) acc[i][j][q] = 0.f;

    const int nch = K >> 5;
    const int lr = tid >> 2;
    const int lc = tid & 3;
    auto load_stage = [&](int s, int c) {
        uint32_t st = sbase + s * STAGE_B;
        int k0 = c * 32;
#pragma unroll
        for (int i = 0; i < 2; i++) {
            int r = lr + i * 64;
            uint32_t sw = (uint32_t)((lc ^ ((r >> 1) & 3)) << 4);
            CP_ASYNC16(st + r * 64 + sw, A + (size_t)(m0 + r) * K + k0 + lc * 8);
        }
#pragma unroll
        for (int i = 0; i < 2; i++) {
            int r = lr + i * 64;
            uint32_t sw = (uint32_t)((lc ^ ((r >> 1) & 3)) << 4);
            CP_ASYNC16(st + 8192 + r * 64 + sw, B + (size_t)(n0 + r) * K + k0 + lc * 8);
        }
        CP_COMMIT();
    };

    load_stage(0, 0);
    if (nch > 1) load_stage(1, 1);
    if (nch > 2) load_stage(2, 2);

    const int lrow = lane & 15;
    const int lhalf = lane >> 4;

    for (int c = 0; c < nch; c++) {
        if (c + 2 < nch)      asm volatile("cp.async.wait_group 2;" ::: "memory");
        else if (c + 1 < nch) asm volatile("cp.async.wait_group 1;" ::: "memory");
        else                  asm volatile("cp.async.wait_group 0;" ::: "memory");
        __syncthreads();
        if (c + 3 < nch) load_stage((c + 3) & 3, c + 3);

        uint32_t sA = sbase + (c & 3) * STAGE_B;
        uint32_t sB = sA + 8192;

        uint32_t a[2][2][4];
#pragma unroll
        for (int kh = 0; kh < 2; kh++)
#pragma unroll
            for (int mt = 0; mt < 2; mt++) {
                int r = warpM * 32 + mt * 16 + lrow;
                int chunk = kh * 2 + lhalf;
                ldmatrix_x4(a[kh][mt], sA + r * 64 + (uint32_t)((chunk ^ ((r >> 1) & 3)) << 4));
            }
#pragma unroll
        for (int kh = 0; kh < 2; kh++) {
            int chunk = kh * 2 + lhalf;
#pragma unroll
            for (int np = 0; np < 4; np++) {
                uint32_t b[4];
                int r = warpN * 64 + np * 16 + lrow;
                ldmatrix_x4(b, sB + r * 64 + (uint32_t)((chunk ^ ((r >> 1) & 3)) << 4));
#pragma unroll
                for (int mt = 0; mt < 2; mt++) {
                    mma_16816(acc[mt][2 * np],     a[kh][mt], b[0], b[2]);
                    mma_16816(acc[mt][2 * np + 1], a[kh][mt], b[1], b[3]);
                }
            }
        }
    }

    const int colq = (lane & 3) * 2;
#pragma unroll
    for (int mt = 0; mt < 2; mt++) {
        int grow0 = m0 + warpM * 32 + mt * 16 + (lane >> 2);
        int grow1 = grow0 + 8;
        int dst0 = (MODE == 1) ? map_row(grow0) : grow0;
        int dst1 = (MODE == 1) ? map_row(grow1) : grow1;
#pragma unroll
        for (int nt = 0; nt < 8; nt++) {
            int gc = n0 + warpN * 64 + nt * 8 + colq;
            float b0 = bias[gc], b1 = bias[gc + 1];
            float v00 = acc[mt][nt][0] + b0, v01 = acc[mt][nt][1] + b1;
            float v10 = acc[mt][nt][2] + b0, v11 = acc[mt][nt][3] + b1;
            if (MODE == 0) {
                *reinterpret_cast<__nv_bfloat162*>(&outb[(size_t)grow0 * N + gc]) =
                    __nv_bfloat162(__float2bfloat16(v00), __float2bfloat16(v01));
                *reinterpret_cast<__nv_bfloat162*>(&outb[(size_t)grow1 * N + gc]) =
                    __nv_bfloat162(__float2bfloat16(v10), __float2bfloat16(v11));
            } else if (MODE == 1) {
                const float2 r0 = *reinterpret_cast<const float2*>(&resid[(size_t)dst0 * N + gc]);
                const float2 r1 = *reinterpret_cast<const float2*>(&resid[(size_t)dst1 * N + gc]);
                *reinterpret_cast<float2*>(&outf[(size_t)dst0 * N + gc]) =
                    make_float2(v00 + r0.x, v01 + r0.y);
                *reinterpret_cast<float2*>(&outf[(size_t)dst1 * N + gc]) =
                    make_float2(v10 + r1.x, v11 + r1.y);
            } else if (MODE == 2) {
                v00 = 0.5f * v00 * (1.0f + erff(v00 * 0.7071067811865475f));
                v01 = 0.5f * v01 * (1.0f + erff(v01 * 0.7071067811865475f));
                v10 = 0.5f * v10 * (1.0f + erff(v10 * 0.7071067811865475f));
                v11 = 0.5f * v11 * (1.0f + erff(v11 * 0.7071067811865475f));
                *reinterpret_cast<__nv_bfloat162*>(&outb[(size_t)grow0 * N + gc]) =
                    __nv_bfloat162(__float2bfloat16(v00), __float2bfloat16(v01));
                *reinterpret_cast<__nv_bfloat162*>(&outb[(size_t)grow1 * N + gc]) =
                    __nv_bfloat162(__float2bfloat16(v10), __float2bfloat16(v11));
            } else {
                const float2 r0 = *reinterpret_cast<const float2*>(&resid[(size_t)grow0 * N + gc]);
                const float2 r1 = *reinterpret_cast<const float2*>(&resid[(size_t)grow1 * N + gc]);
                *reinterpret_cast<float2*>(&outf[(size_t)grow0 * N + gc]) =
                    make_float2(v00 + r0.x, v01 + r0.y);
                *reinterpret_cast<float2*>(&outf[(size_t)grow1 * N + gc]) =
                    make_float2(v10 + r1.x, v11 + r1.y);
            }
        }
    }
}

// ---------------- tensor-core windowed attention: block = (2 windows, head) ----------------
#define TBL_STRIDE 144
__global__ __launch_bounds__(256, 4)
void attn_mma(const __nv_bfloat16* __restrict__ qkv,
              const __nv_bfloat16* __restrict__ tbl,
              __nv_bfloat16* __restrict__ out,
              int win_base) {
    __shared__ __align__(1024) char sq[2][4096];
    __shared__ __align__(1024) char sk[2][4096];
    __shared__ __align__(1024) char sv[2][4096];
    __shared__ __align__(16)   char stbl[64 * TBL_STRIDE];

    const int tid = threadIdx.x;
    const int sub = tid >> 7;
    const int t2 = tid & 127;
    const int lane = tid & 31, w4 = (tid >> 5) & 3;
    const int win = win_base + blockIdx.x + sub * 256;
    const int head = blockIdx.y;
    const uint32_t qb = smem_u32(sq[sub]), kb = smem_u32(sk[sub]), vb = smem_u32(sv[sub]);
    const uint32_t tbase = smem_u32(stbl);

    const char* basep = reinterpret_cast<const char*>(qkv + (size_t)win * NWN * 1152 + head * HD);
#pragma unroll
    for (int i = t2; i < 256; i += 128) {
        int r = i >> 2, c = i & 3;
        int n = (r < NWN) ? 16 : 0;
        const char* p = basep + (size_t)r * 2304;
        uint32_t sw = (uint32_t)((c ^ ((r >> 1) & 3)) << 4);
        CP_ASYNC16_Z(qb + r * 64 + sw, p + c * 16, n);
        CP_ASYNC16_Z(kb + r * 64 + sw, p + 768 + c * 16, n);
        CP_ASYNC16_Z(vb + r * 64 + sw, p + 1536 + c * 16, n);
    }
    CP_COMMIT();

    {
        const char* g = reinterpret_cast<const char*>(
            tbl + (((size_t)((blockIdx.x & 15) * 12 + head)) << 12));
#pragma unroll
        for (int i = tid; i < 512; i += 256) {
            int r = i >> 3, c16 = i & 7;
            CP_ASYNC16(tbase + r * TBL_STRIDE + c16 * 16, g + i * 16);
        }
    }
    CP_COMMIT();

    CP_WAIT1();
    __syncthreads();

    const int lrow = lane & 15, lhalf = lane >> 4;

    float sacc[8][4];
#pragma unroll
    for (int t = 0; t < 8; t++)
#pragma unroll
        for (int q = 0; q < 4; q++) sacc[t][q] = 0.f;

    uint32_t af[2][4];
#pragma unroll
    for (int kh = 0; kh < 2; kh++) {
        int r = w4 * 16 + lrow;
        int chunk = kh * 2 + lhalf;
        ldmatrix_x4(af[kh], qb + r * 64 + (uint32_t)((chunk ^ ((r >> 1) & 3)) << 4));
    }
#pragma unroll
    for (int kh = 0; kh < 2; kh++) {
        int chunk = kh * 2 + lhalf;
        uint32_t b[4][4];
#pragma unroll
        for (int np = 0; np < 4; np++) {
            int r = np * 16 + lrow;
            ldmatrix_x4(b[np], kb + r * 64 + (uint32_t)((chunk ^ ((r >> 1) & 3)) << 4));
        }
#pragma unroll
        for (int np = 0; np < 4; np++) {
            mma_16816(sacc[2 * np],     af[kh], b[np][0], b[np][2]);
            mma_16816(sacc[2 * np + 1], af[kh], b[np][1], b[np][3]);
        }
    }

    CP_WAIT0();
    __syncthreads();

    const int r0 = w4 * 16 + (lane >> 2), r1 = r0 + 8;
    const int c0 = 2 * (lane & 3);
    const uint32_t tb0 = tbase + r0 * TBL_STRIDE + c0 * 2;
#pragma unroll
    for (int t = 0; t < 8; t++) {
        uint32_t u0, u1;
        asm volatile("ld.shared.b32 %0, [%1];" : "=r"(u0) : "r"(tb0 + 16 * t));
        asm volatile("ld.shared.b32 %0, [%1];" : "=r"(u1) : "r"(tb0 + 8 * TBL_STRIDE + 16 * t));
        float2 b0 = __bfloat1622float2(*reinterpret_cast<__nv_bfloat162*>(&u0));
        float2 b1 = __bfloat1622float2(*reinterpret_cast<__nv_bfloat162*>(&u1));
        sacc[t][0] += b0.x; sacc[t][1] += b0.y;
        sacc[t][2] += b1.x; sacc[t][3] += b1.y;
    }

    float mx0 = -1e30f, mx1 = -1e30f;
#pragma unroll
    for (int t = 0; t < 8; t++) {
        mx0 = fmaxf(mx0, fmaxf(sacc[t][0], sacc[t][1]));
        mx1 = fmaxf(mx1, fmaxf(sacc[t][2], sacc[t][3]));
    }
    mx0 = fmaxf(mx0, __shfl_xor_sync(0xffffffffu, mx0, 1));
    mx0 = fmaxf(mx0, __shfl_xor_sync(0xffffffffu, mx0, 2));
    mx1 = fmaxf(mx1, __shfl_xor_sync(0xffffffffu, mx1, 1));
    mx1 = fmaxf(mx1, __shfl_xor_sync(0xffffffffu, mx1, 2));
    float s0 = 0.f, s1 = 0.f;
#pragma unroll
    for (int t = 0; t < 8; t++) {
        float e0 = __expf(sacc[t][0] - mx0); sacc[t][0] = e0; s0 += e0;
        float e1 = __expf(sacc[t][1] - mx0); sacc[t][1] = e1; s0 += e1;
        float e2 = __expf(sacc[t][2] - mx1); sacc[t][2] = e2; s1 += e2;
        float e3 = __expf(sacc[t][3] - mx1); sacc[t][3] = e3; s1 += e3;
    }
    s0 += __shfl_xor_sync(0xffffffffu, s0, 1);
    s0 += __shfl_xor_sync(0xffffffffu, s0, 2);
    s1 += __shfl_xor_sync(0xffffffffu, s1, 1);
    s1 += __shfl_xor_sync(0xffffffffu, s1, 2);
    float inv0 = 1.f / s0, inv1 = 1.f / s1;
#pragma unroll
    for (int t = 0; t < 8; t++) {
        sacc[t][0] *= inv0; sacc[t][1] *= inv0;
        sacc[t][2] *= inv1; sacc[t][3] *= inv1;
    }

    float oacc[4][4];
#pragma unroll
    for (int t = 0; t < 4; t++)
#pragma unroll
        for (int q = 0; q < 4; q++) oacc[t][q] = 0.f;

#pragma unroll
    for (int j = 0; j < 4; j++) {
        uint32_t pa[4];
        pa[0] = pack_bf16(sacc[2 * j][0],     sacc[2 * j][1]);
        pa[1] = pack_bf16(sacc[2 * j][2],     sacc[2 * j][3]);
        pa[2] = pack_bf16(sacc[2 * j + 1][0], sacc[2 * j + 1][1]);
        pa[3] = pack_bf16(sacc[2 * j + 1][2], sacc[2 * j + 1][3]);
        int vr = j * 16 + ((lane >> 3) & 1) * 8 + (lane & 7);
        uint32_t t4[2][4];
#pragma unroll
        for (int dblk = 0; dblk < 2; dblk++) {
            int chunk = dblk * 2 + (lane >> 4);
            ldmatrix_x4_trans(t4[dblk], vb + vr * 64 + (uint32_t)((chunk ^ ((vr >> 1) & 3)) << 4));
        }
#pragma unroll
        for (int dblk = 0; dblk < 2; dblk++) {
            mma_16816(oacc[2 * dblk],     pa, t4[dblk][0], t4[dblk][1]);
            mma_16816(oacc[2 * dblk + 1], pa, t4[dblk][2], t4[dblk][3]);
        }
    }

    if (r0 < NWN) {
        size_t ob = ((size_t)win * NWN + r0) * DIM + head * HD;
#pragma unroll
        for (int t = 0; t < 4; t++) {
            int d = 8 * t + c0;
            *reinterpret_cast<__nv_bfloat162*>(&out[ob + d]) =
                __nv_bfloat162(__float2bfloat16(oacc[t][0]), __float2bfloat16(oacc[t][1]));
        }
    }
    if (r1 < NWN) {
        size_t ob = ((size_t)win * NWN + r1) * DIM + head * HD;
#pragma unroll
        for (int t = 0; t < 4; t++) {
            int d = 8 * t + c0;
            *reinterpret_cast<__nv_bfloat162*>(&out[ob + d]) =
                __nv_bfloat162(__float2bfloat16(oacc[t][2]), __float2bfloat16(oacc[t][3]));
        }
    }
}

// ---------------- launch: two-stream half pipelining ----------------
extern "C" void kernel_launch(void* const* d_in, const int* in_sizes, int n_in,
                              void* d_out, int out_size) {
    const float* x      = (const float*)d_in[0];
    const float* n1g    = (const float*)d_in[1];
    const float* n1b    = (const float*)d_in[2];
    const float* qkv_w  = (const float*)d_in[3];
    const float* qkv_b  = (const float*)d_in[4];
    const float* proj_w = (const float*)d_in[5];
    const float* proj_b = (const float*)d_in[6];
    const float* rpb    = (const float*)d_in[7];
    const float* n2g    = (const float*)d_in[8];
    const float* n2b    = (const float*)d_in[9];
    const float* fc1_w  = (const float*)d_in[10];
    const float* fc1_b  = (const float*)d_in[11];
    const float* fc2_w  = (const float*)d_in[12];
    const float* fc2_b  = (const float*)d_in[13];
    float* out = (float*)d_out;

    __nv_bfloat16 *xw, *qkv, *att, *m, *h1, *wqkv, *wproj, *wfc1, *wfc2, *tbl;
    float *y, *bqkv;
    cudaGetSymbolAddress((void**)&xw,    g_xw);
    cudaGetSymbolAddress((void**)&qkv,   g_qkv);
    cudaGetSymbolAddress((void**)&att,   g_att);
    cudaGetSymbolAddress((void**)&y,     g_y);
    cudaGetSymbolAddress((void**)&m,     g_m);
    cudaGetSymbolAddress((void**)&h1,    g_h1);
    cudaGetSymbolAddress((void**)&wqkv,  g_wqkv);
    cudaGetSymbolAddress((void**)&wproj, g_wproj);
    cudaGetSymbolAddress((void**)&wfc1,  g_wfc1);
    cudaGetSymbolAddress((void**)&wfc2,  g_wfc2);
    cudaGetSymbolAddress((void**)&bqkv,  g_bqkv);
    cudaGetSymbolAddress((void**)&tbl,   g_tbl);

    cudaFuncSetAttribute(mma_gemm<0>, cudaFuncAttributeMaxDynamicSharedMemorySize, GEMM_SMEM);
    cudaFuncSetAttribute(mma_gemm<1>, cudaFuncAttributeMaxDynamicSharedMemorySize, GEMM_SMEM);
    cudaFuncSetAttribute(mma_gemm<2>, cudaFuncAttributeMaxDynamicSharedMemorySize, GEMM_SMEM);
    cudaFuncSetAttribute(mma_gemm<3>, cudaFuncAttributeMaxDynamicSharedMemorySize, GEMM_SMEM);

    static cudaStream_t s1 = nullptr;
    static cudaEvent_t evFork = nullptr, evJoin = nullptr, evA = nullptr, evB = nullptr;
    if (!s1) {
        cudaStreamCreateWithFlags(&s1, cudaStreamNonBlocking);
        cudaEventCreateWithFlags(&evFork, cudaEventDisableTiming);
        cudaEventCreateWithFlags(&evJoin, cudaEventDisableTiming);
        cudaEventCreateWithFlags(&evA, cudaEventDisableTiming);
        cudaEventCreateWithFlags(&evB, cudaEventDisableTiming);
    }

    // fork: cvt_all concurrent with LN1
    cudaEventRecord(evFork, 0);
    cudaStreamWaitEvent(s1, evFork, 0);
    cvt_all<<<1920, 256, 0, s1>>>(qkv_w, proj_w, fc1_w, fc2_w, qkv_b, rpb);
    cudaEventRecord(evJoin, s1);

    ln_kernel<true><<<NTOK / 8, 256>>>(x, n1g, n1b, xw);
    cudaStreamWaitEvent(0, evJoin, 0);

    // ---- half A: QKV on main, then full chain A on side stream ----
    mma_gemm<0><<<dim3(9, 196), 256, GEMM_SMEM>>>(xw, wqkv, bqkv, nullptr, qkv, nullptr, 3 * DIM, DIM, 0);
    cudaEventRecord(evA, 0);
    cudaStreamWaitEvent(s1, evA, 0);
    attn_mma<<<dim3(256, HEADS), 256, 0, s1>>>(qkv, tbl, att, 0);
    mma_gemm<1><<<dim3(3, 196), 256, GEMM_SMEM, s1>>>(att, wproj, proj_b, x, nullptr, y, DIM, DIM, 0);
    ln_kernel<false><<<HTOK / 8, 256, 0, s1>>>(y, n2g, n2b, m);
    mma_gemm<2><<<dim3(12, 196), 256, GEMM_SMEM, s1>>>(m, wfc1, fc1_b, nullptr, h1, nullptr, 4 * DIM, DIM, 0);
    mma_gemm<3><<<dim3(3, 196), 256, GEMM_SMEM, s1>>>(h1, wfc2, fc2_b, y, nullptr, out, DIM, 4 * DIM, 0);
    cudaEventRecord(evB, s1);

    // ---- half B: full chain on main stream ----
    mma_gemm<0><<<dim3(9, 196), 256, GEMM_SMEM>>>(xw, wqkv, bqkv, nullptr, qkv, nullptr, 3 * DIM, DIM, 196);
    attn_mma<<<dim3(256, HEADS), 256>>>(qkv, tbl, att, 512);
    mma_gemm<1><<<dim3(3, 196), 256, GEMM_SMEM>>>(att, wproj, proj_b, x, nullptr, y, DIM, DIM, 196);
    ln_kernel<false><<<HTOK / 8, 256>>>(y + (size_t)HTOK * DIM, n2g, n2b, m + (size_t)HTOK * DIM);
    mma_gemm<2><<<dim3(12, 196), 256, GEMM_SMEM>>>(m, wfc1, fc1_b, nullptr, h1, nullptr, 4 * DIM, DIM, 196);
    mma_gemm<3><<<dim3(3, 196), 256, GEMM_SMEM>>>(h1, wfc2, fc2_b, y, nullptr, out, DIM, 4 * DIM, 196);

    // join half A before returning
    cudaStreamWaitEvent(0, evB, 0);
}